// round 9
// baseline (speedup 1.0000x reference)
#include <cuda_runtime.h>
#include <cuda_bf16.h>
#include <cstdint>

#define CDIM     64
#define KSLOTS   27
#define TILE     128
#define NMAX     65536
#define EPAD     (KSLOTS * TILE)
#define EMAX     (1572864 + EPAD)
#define MAXSEG   1024
#define CONVGX   22          // CTAs per k-bin (grid = CONVGX x 27)

// smem layout for k_conv: W once, X double-buffered; rows padded to 144B
#define SM_WH    0
#define SM_WL    9216
#define SM_XB    18432                    // X buffer b at SM_XB + b*36864
#define XBUF     36864                    // per-buffer: hi 18432 + lo 18432
#define SMEM_TOT (SM_XB + 2 * XBUF)       // 92160 bytes

// ---------------- device scratch (static: zero-initialized at load) ----------
__device__ float  g_bufA[(size_t)NMAX * CDIM];   // conv accumulators (fp32)
__device__ uint4  g_xh1[(size_t)NMAX * 8], g_xl1[(size_t)NMAX * 8]; // x split
__device__ uint4  g_xh2[(size_t)NMAX * 8], g_xl2[(size_t)NMAX * 8]; // act split
__device__ uint4  g_w1s[KSLOTS * 1024], g_w2s[KSLOTS * 1024]; // Wt split hi/lo
__device__ int2   g_sij[EMAX];                   // sorted (target, source); pad=(-1,0)
__device__ int    g_hist[KSLOTS];                // invariant: 0 between calls
__device__ int    g_aoff[KSLOTS + 1];
__device__ int    g_cursor[KSLOTS];
__device__ int    g_segoff[MAXSEG + 1];
__device__ double g_s1[MAXSEG], g_s2[MAXSEG];
__device__ float  g_mean[MAXSEG], g_invs[MAXSEG];

// ---------------- helpers -----------------------------------------------------
__device__ __forceinline__ uint32_t smem_u32(const void* p) {
    uint32_t a;
    asm("{ .reg .u64 t; cvta.to.shared.u64 t, %1; cvt.u32.u64 %0, t; }"
        : "=r"(a) : "l"(p));
    return a;
}
__device__ __forceinline__ void cpa16(uint32_t d, const void* s) {
    asm volatile("cp.async.cg.shared.global [%0], [%1], 16;"
                 :: "r"(d), "l"(s) : "memory");
}
#define CPA_COMMIT() asm volatile("cp.async.commit_group;" ::: "memory")
#define CPA_WAIT0()  asm volatile("cp.async.wait_group 0;" ::: "memory")
#define CPA_WAIT1()  asm volatile("cp.async.wait_group 1;" ::: "memory")

#define LDMX4(r, addr) \
    asm volatile("ldmatrix.sync.aligned.m8n8.x4.shared.b16 {%0,%1,%2,%3}, [%4];" \
        : "=r"((r)[0]), "=r"((r)[1]), "=r"((r)[2]), "=r"((r)[3]) : "r"(addr))

#define MMA16816(d, a, b0, b1) \
    asm volatile("mma.sync.aligned.m16n8k16.row.col.f32.bf16.bf16.f32 " \
        "{%0,%1,%2,%3}, {%4,%5,%6,%7}, {%8,%9}, {%0,%1,%2,%3};" \
        : "+f"((d)[0]), "+f"((d)[1]), "+f"((d)[2]), "+f"((d)[3]) \
        : "r"((a)[0]), "r"((a)[1]), "r"((a)[2]), "r"((a)[3]), "r"(b0), "r"(b1))

// bf16 hi/lo split of a float pair -> packed u32s
__device__ __forceinline__ void split2(float a, float b, unsigned& h, unsigned& l) {
    __nv_bfloat16 ha = __float2bfloat16_rn(a), hb = __float2bfloat16_rn(b);
    float ra = a - __bfloat162float(ha);
    float rb = b - __bfloat162float(hb);
    __nv_bfloat16 la = __float2bfloat16_rn(ra), lb = __float2bfloat16_rn(rb);
    h = (unsigned)__bfloat16_as_ushort(ha) | ((unsigned)__bfloat16_as_ushort(hb) << 16);
    l = (unsigned)__bfloat16_as_ushort(la) | ((unsigned)__bfloat16_as_ushort(lb) << 16);
}

// ---------------- prep: pad fill + hist + x split + W transpose/split --------
__global__ void k_prep(const int* __restrict__ ek, int E, int fillN,
                       const float* __restrict__ x, int N,
                       const float* __restrict__ W1, const float* __restrict__ W2) {
    __shared__ int h[KSLOTS];
    if (threadIdx.x < KSLOTS) h[threadIdx.x] = 0;
    __syncthreads();
    int stride = gridDim.x * blockDim.x;
    int idx0   = blockIdx.x * blockDim.x + threadIdx.x;

    for (int e = idx0; e < fillN; e += stride) g_sij[e] = make_int2(-1, 0);
    for (int e = idx0; e < E; e += stride) atomicAdd(&h[ek[e]], 1);

    // x rows -> bf16 hi/lo
    for (int p = idx0; p < N; p += stride) {
        const float4* xr = reinterpret_cast<const float4*>(x + (size_t)p * CDIM);
        #pragma unroll
        for (int g = 0; g < 8; g++) {
            float4 a = __ldg(xr + 2 * g), b = __ldg(xr + 2 * g + 1);
            uint4 oh, ol;
            split2(a.x, a.y, oh.x, ol.x);
            split2(a.z, a.w, oh.y, ol.y);
            split2(b.x, b.y, oh.z, ol.z);
            split2(b.z, b.w, oh.w, ol.w);
            g_xh1[(size_t)p * 8 + g] = oh;
            g_xl1[(size_t)p * 8 + g] = ol;
        }
    }

    // W -> transposed Wt[o][c], split hi/lo: per k, 4096 ushort hi then 4096 lo
    int wtot = 2 * KSLOTS * CDIM * CDIM;
    for (int q = idx0; q < wtot; q += stride) {
        int which = (q >= KSLOTS * CDIM * CDIM);
        int rem   = which ? q - KSLOTS * CDIM * CDIM : q;
        int kk = rem >> 12;
        int cc = (rem & 4095) >> 6;
        int oo = rem & 63;
        const float* W = which ? W2 : W1;
        float v = __ldg(W + (size_t)kk * 4096 + cc * 64 + oo);
        __nv_bfloat16 hb = __float2bfloat16_rn(v);
        float r = v - __bfloat162float(hb);
        __nv_bfloat16 lb = __float2bfloat16_rn(r);
        unsigned short* dst = reinterpret_cast<unsigned short*>(which ? g_w2s : g_w1s);
        dst[(size_t)kk * 8192 + oo * 64 + cc]        = __bfloat16_as_ushort(hb);
        dst[(size_t)kk * 8192 + 4096 + oo * 64 + cc] = __bfloat16_as_ushort(lb);
    }

    __syncthreads();
    if (threadIdx.x < KSLOTS) atomicAdd(&g_hist[threadIdx.x], h[threadIdx.x]);
}

__global__ void k_scan(const int* __restrict__ ss, int B, int N) {
    if (threadIdx.x == 0 && blockIdx.x == 0) {
        int off = 0;
        for (int q = 0; q < KSLOTS; q++) {
            g_aoff[q]   = off;
            g_cursor[q] = off;
            off += ((g_hist[q] + TILE - 1) / TILE) * TILE;
        }
        g_aoff[KSLOTS] = off;
        int p = 0;
        for (int b = 0; b < B; b++) { g_segoff[b] = p; p += ss[b]; }
        g_segoff[B] = N;
        for (int b = 0; b < B; b++) { g_s1[b] = 0.0; g_s2[b] = 0.0; }
    }
}

// block-aggregated counting-sort scatter: 1 global atomic per (block, slot)
__global__ void k_scatter(const int* __restrict__ i, const int* __restrict__ j,
                          const int* __restrict__ k, int E) {
    __shared__ int sh[KSLOTS], sbase[KSLOTS];
    int tid = threadIdx.x;
    if (tid < KSLOTS) sh[tid] = 0;
    __syncthreads();
    int e = blockIdx.x * blockDim.x + tid;
    int kk = 0, rank = 0;
    bool valid = (e < E);
    if (valid) {
        kk   = k[e];
        rank = atomicAdd(&sh[kk], 1);
    }
    __syncthreads();
    if (tid < KSLOTS && sh[tid] > 0)
        sbase[tid] = atomicAdd(&g_cursor[tid], sh[tid]);
    __syncthreads();
    if (valid) {
        int pos = sbase[kk] + rank;
        g_sij[pos] = make_int2(i[e], j[e]);
    }
    if (blockIdx.x == 0 && tid < KSLOTS) g_hist[tid] = 0;   // reset for replay
}

// ---------------- tensor-core conv: k-bin persistent, B frags in registers ----
// grid = (CONVGX, KSLOTS). CTA (bx, k) handles tiles t0+bx, t0+bx+GX, ... of
// bin k. W[k] staged + its B fragments ldmatrix'd ONCE, held in 128 regs.
// X double-buffered via cp.async; D scattered from fragments as float4 REDs.
__global__ void __launch_bounds__(128, 1)
k_conv(const uint4* __restrict__ gXh, const uint4* __restrict__ gXl,
       const uint4* __restrict__ gW, float* __restrict__ out) {
    extern __shared__ char smem[];
    int kk = blockIdx.y;
    int t0 = g_aoff[kk] / TILE, t1 = g_aoff[kk + 1] / TILE;
    int t  = t0 + blockIdx.x;
    if (t >= t1) return;

    int tid = threadIdx.x, w = tid >> 5, lane = tid & 31;
    uint32_t sb = smem_u32(smem);

    // group 0: W[k] hi/lo (rows o, stride 144B) + first X tile into buf0
    const uint4* ws = gW + (size_t)kk * 1024;
    #pragma unroll
    for (int q = 0; q < 4; q++) {
        int idx = tid + 128 * q;
        int o = idx >> 3, c8 = idx & 7;
        cpa16(sb + SM_WH + o * 144 + c8 * 16, ws + idx);
        cpa16(sb + SM_WL + o * 144 + c8 * 16, ws + 512 + idx);
    }
    {
        int jj = g_sij[t * TILE + tid].y;
        const uint4* xh = gXh + (size_t)jj * 8;
        const uint4* xl = gXl + (size_t)jj * 8;
        uint32_t xb = sb + SM_XB;
        #pragma unroll
        for (int q = 0; q < 8; q++) {
            cpa16(xb + tid * 144 + q * 16, xh + q);
            cpa16(xb + 18432 + tid * 144 + q * 16, xl + q);
        }
    }
    CPA_COMMIT();
    CPA_WAIT0();
    __syncthreads();

    // B fragments: load once, keep in registers for whole CTA lifetime
    uint32_t Bh[4][4][4], Bl[4][4][4];     // [np][ks][4]
    {
        int nsub  = (lane & 7) + 8 * (lane >> 4);
        int kbyte = ((lane >> 3) & 1) * 16;
        #pragma unroll
        for (int np = 0; np < 4; np++) {
            uint32_t bh = sb + SM_WH + (np * 16 + nsub) * 144 + kbyte;
            uint32_t bl = sb + SM_WL + (np * 16 + nsub) * 144 + kbyte;
            #pragma unroll
            for (int ks = 0; ks < 4; ks++) {
                LDMX4(Bh[np][ks], bh + ks * 32);
                LDMX4(Bl[np][ks], bl + ks * 32);
            }
        }
    }

    int arow  = lane & 15;
    int abyte = (lane >> 4) * 16;
    int buf = 0;

    for (; t < t1; t += gridDim.x, buf ^= 1) {
        int tn = t + gridDim.x;
        if (tn < t1) {
            int jj = g_sij[tn * TILE + tid].y;
            const uint4* xh = gXh + (size_t)jj * 8;
            const uint4* xl = gXl + (size_t)jj * 8;
            uint32_t xb = sb + SM_XB + (buf ^ 1) * XBUF;
            #pragma unroll
            for (int q = 0; q < 8; q++) {
                cpa16(xb + tid * 144 + q * 16, xh + q);
                cpa16(xb + 18432 + tid * 144 + q * 16, xl + q);
            }
            CPA_COMMIT();
            CPA_WAIT1();
        } else {
            CPA_WAIT0();
        }
        __syncthreads();

        float acc[2][8][4];
        #pragma unroll
        for (int a = 0; a < 2; a++)
            #pragma unroll
            for (int b = 0; b < 8; b++)
                #pragma unroll
                for (int c = 0; c < 4; c++) acc[a][b][c] = 0.f;

        uint32_t xbase = sb + SM_XB + buf * XBUF;
        #pragma unroll
        for (int ks = 0; ks < 4; ks++) {
            uint32_t ah[2][4], al[2][4];
            #pragma unroll
            for (int mt = 0; mt < 2; mt++) {
                int row = w * 32 + mt * 16 + arow;
                LDMX4(ah[mt], xbase + row * 144 + abyte + ks * 32);
                LDMX4(al[mt], xbase + 18432 + row * 144 + abyte + ks * 32);
            }
            #pragma unroll
            for (int np = 0; np < 4; np++) {
                #pragma unroll
                for (int mt = 0; mt < 2; mt++) {
                    float* d0 = acc[mt][2 * np];
                    float* d1 = acc[mt][2 * np + 1];
                    MMA16816(d0, ah[mt], Bh[np][ks][0], Bh[np][ks][1]);
                    MMA16816(d0, al[mt], Bh[np][ks][0], Bh[np][ks][1]);
                    MMA16816(d0, ah[mt], Bl[np][ks][0], Bl[np][ks][1]);
                    MMA16816(d1, ah[mt], Bh[np][ks][2], Bh[np][ks][3]);
                    MMA16816(d1, al[mt], Bh[np][ks][2], Bh[np][ks][3]);
                    MMA16816(d1, ah[mt], Bl[np][ks][2], Bl[np][ks][3]);
                }
            }
        }

        // scatter: lane-pair shuffle -> float4 REDs
        // even lane: row r, cols [base..base+3]; odd lane: row r+8
        int odd  = lane & 1;
        int cbase = 4 * ((lane & 3) >> 1);
        int tb = t * TILE;
        #pragma unroll
        for (int mt = 0; mt < 2; mt++) {
            int row = w * 32 + mt * 16 + (lane >> 2) + odd * 8;
            int ii  = g_sij[tb + row].x;
            float* orow = out + (size_t)(ii < 0 ? 0 : ii) * CDIM;
            #pragma unroll
            for (int nt = 0; nt < 8; nt++) {
                float d0 = acc[mt][nt][0], d1 = acc[mt][nt][1];
                float d2 = acc[mt][nt][2], d3 = acc[mt][nt][3];
                float gx = odd ? d0 : d2, gy = odd ? d1 : d3;
                gx = __shfl_xor_sync(0xffffffffu, gx, 1);
                gy = __shfl_xor_sync(0xffffffffu, gy, 1);
                float4 v = odd ? make_float4(gx, gy, d2, d3)
                               : make_float4(d0, d1, gx, gy);
                if (ii >= 0)
                    atomicAdd(reinterpret_cast<float4*>(orow + nt * 8 + cbase), v);
            }
        }
        __syncthreads();   // protect X buffer before next prefetch overwrites
    }
}

// ---------------- ragged LayerNorm ------------------------------------------
__global__ void k_stats(const float* __restrict__ v) {
    int seg = blockIdx.x;
    long long e0 = (long long)g_segoff[seg] * CDIM;
    long long e1 = (long long)g_segoff[seg + 1] * CDIM;
    double s1 = 0.0, s2 = 0.0;
    long long stride = (long long)gridDim.y * blockDim.x;
    for (long long idx = e0 + (long long)blockIdx.y * blockDim.x + threadIdx.x;
         idx < e1; idx += stride) {
        double d = (double)v[idx];
        s1 += d;
        s2 += d * d;
    }
    #pragma unroll
    for (int o = 16; o; o >>= 1) {
        s1 += __shfl_down_sync(0xffffffffu, s1, o);
        s2 += __shfl_down_sync(0xffffffffu, s2, o);
    }
    __shared__ double w1[8], w2[8];
    int wid = threadIdx.x >> 5, lid = threadIdx.x & 31;
    if (lid == 0) { w1[wid] = s1; w2[wid] = s2; }
    __syncthreads();
    if (threadIdx.x == 0) {
        double a = 0.0, b = 0.0;
        int nw = blockDim.x >> 5;
        for (int q = 0; q < nw; q++) { a += w1[q]; b += w2[q]; }
        atomicAdd(&g_s1[seg], a);
        atomicAdd(&g_s2[seg], b);
    }
}

__global__ void k_finalize(int B) {
    int s = blockIdx.x * blockDim.x + threadIdx.x;
    if (s < B) {
        double cnt  = (double)(g_segoff[s + 1] - g_segoff[s]) * (double)CDIM;
        double mean = g_s1[s] / cnt;
        double var  = g_s2[s] / cnt - mean * mean;
        g_mean[s] = (float)mean;
        g_invs[s] = rsqrtf((float)var + 1e-5f);
    }
}

__device__ __forceinline__ int find_seg(int p, int B) {
    int s = 0;
    #pragma unroll 1
    while (s + 1 < B && __ldg(&g_segoff[s + 1]) <= p) s++;
    return s;
}

// LN1 + relu -> bf16 hi/lo split; re-zeroes accumulator + layer-2 stats
__global__ void k_norm_relu(float* __restrict__ v,
                            const float* __restrict__ gamma,
                            const float* __restrict__ beta,
                            uint4* __restrict__ oh, uint4* __restrict__ ol,
                            int N, int B) {
    if (blockIdx.x == 0 && threadIdx.x < B) {
        g_s1[threadIdx.x] = 0.0;
        g_s2[threadIdx.x] = 0.0;
    }
    int total = N * (CDIM / 4);
    float4 z = make_float4(0.f, 0.f, 0.f, 0.f);
    for (int q = blockIdx.x * blockDim.x + threadIdx.x; q < total;
         q += gridDim.x * blockDim.x) {
        int p  = q >> 4;
        int c4 = (q & 15) << 2;
        int s  = find_seg(p, B);
        float mu = g_mean[s], inv = g_invs[s];
        float4 x4 = reinterpret_cast<float4*>(v)[q];
        reinterpret_cast<float4*>(v)[q] = z;   // re-zero for conv2
        float4 gg = __ldg(reinterpret_cast<const float4*>(gamma + c4));
        float4 bb = __ldg(reinterpret_cast<const float4*>(beta + c4));
        float r0 = fmaxf(fmaf((x4.x - mu) * inv, gg.x, bb.x), 0.f);
        float r1 = fmaxf(fmaf((x4.y - mu) * inv, gg.y, bb.y), 0.f);
        float r2 = fmaxf(fmaf((x4.z - mu) * inv, gg.z, bb.z), 0.f);
        float r3 = fmaxf(fmaf((x4.w - mu) * inv, gg.w, bb.w), 0.f);
        uint2 hh, ll;
        split2(r0, r1, hh.x, ll.x);
        split2(r2, r3, hh.y, ll.y);
        reinterpret_cast<uint2*>(oh)[(size_t)p * 16 + (q & 15)] = hh;
        reinterpret_cast<uint2*>(ol)[(size_t)p * 16 + (q & 15)] = ll;
    }
}

// LN2 + residual + relu; re-zeroes accumulator for the next replay
__global__ void k_norm_res_relu(float* __restrict__ v,
                                const float* __restrict__ gamma,
                                const float* __restrict__ beta,
                                const float* __restrict__ xin,
                                float* __restrict__ o, int N, int B) {
    int total = N * (CDIM / 4);
    float4 z = make_float4(0.f, 0.f, 0.f, 0.f);
    for (int q = blockIdx.x * blockDim.x + threadIdx.x; q < total;
         q += gridDim.x * blockDim.x) {
        int p  = q >> 4;
        int c4 = (q & 15) << 2;
        int s  = find_seg(p, B);
        float mu = g_mean[s], inv = g_invs[s];
        float4 x4 = reinterpret_cast<float4*>(v)[q];
        reinterpret_cast<float4*>(v)[q] = z;   // re-zero for next call
        float4 rx = __ldg(reinterpret_cast<const float4*>(xin) + q);
        float4 gg = __ldg(reinterpret_cast<const float4*>(gamma + c4));
        float4 bb = __ldg(reinterpret_cast<const float4*>(beta + c4));
        float4 r;
        r.x = fmaxf(fmaf((x4.x - mu) * inv, gg.x, bb.x) + rx.x, 0.f);
        r.y = fmaxf(fmaf((x4.y - mu) * inv, gg.y, bb.y) + rx.y, 0.f);
        r.z = fmaxf(fmaf((x4.z - mu) * inv, gg.z, bb.z) + rx.z, 0.f);
        r.w = fmaxf(fmaf((x4.w - mu) * inv, gg.w, bb.w) + rx.w, 0.f);
        reinterpret_cast<float4*>(o)[q] = r;
    }
}

// ---------------- host-side launch sequence ---------------------------------
extern "C" void kernel_launch(void* const* d_in, const int* in_sizes, int n_in,
                              void* d_out, int out_size) {
    (void)n_in; (void)out_size;
    const float* x  = (const float*)d_in[0];
    const float* W1 = (const float*)d_in[1];
    const float* g1 = (const float*)d_in[2];
    const float* b1 = (const float*)d_in[3];
    const float* W2 = (const float*)d_in[4];
    const float* g2 = (const float*)d_in[5];
    const float* b2 = (const float*)d_in[6];
    const int*   ei = (const int*)d_in[7];
    const int*   ej = (const int*)d_in[8];
    const int*   ek = (const int*)d_in[9];
    const int*   ss = (const int*)d_in[10];

    int N = in_sizes[0] / CDIM;
    int E = in_sizes[7];
    int B = in_sizes[10];
    float* out = (float*)d_out;

    float* pA; cudaGetSymbolAddress((void**)&pA, g_bufA);
    uint4 *xh1, *xl1, *xh2, *xl2, *w1s, *w2s;
    cudaGetSymbolAddress((void**)&xh1, g_xh1);
    cudaGetSymbolAddress((void**)&xl1, g_xl1);
    cudaGetSymbolAddress((void**)&xh2, g_xh2);
    cudaGetSymbolAddress((void**)&xl2, g_xl2);
    cudaGetSymbolAddress((void**)&w1s, g_w1s);
    cudaGetSymbolAddress((void**)&w2s, g_w2s);

    cudaFuncSetAttribute(k_conv, cudaFuncAttributeMaxDynamicSharedMemorySize, SMEM_TOT);

    int fillN = E + EPAD; if (fillN > EMAX) fillN = EMAX;
    int statB = (B + 31) / 32;
    int sgrid = (E + 255) / 256;
    dim3 cgrid(CONVGX, KSLOTS);

    // replay-state invariants: g_hist=0 (end of k_scatter), g_bufA=0 (LN epilogues)
    k_prep<<<1024, 256>>>(ek, E, fillN, x, N, W1, W2);            // L1
    k_scan<<<1, 1>>>(ss, B, N);                                    // L2
    k_scatter<<<sgrid, 256>>>(ei, ej, ek, E);                      // L3

    k_conv<<<cgrid, 128, SMEM_TOT>>>(xh1, xl1, w1s, pA);           // L4 (profiled)
    k_stats<<<dim3(B, 128), 256>>>(pA);                            // L5
    k_finalize<<<statB, 32>>>(B);                                  // L6
    k_norm_relu<<<512, 256>>>(pA, g1, b1, xh2, xl2, N, B);         // L7

    k_conv<<<cgrid, 128, SMEM_TOT>>>(xh2, xl2, w2s, pA);           // L8
    k_stats<<<dim3(B, 128), 256>>>(pA);                            // L9
    k_finalize<<<statB, 32>>>(B);                                  // L10
    k_norm_res_relu<<<512, 256>>>(pA, g2, b2, x, out, N, B);       // L11
}

// round 10
// speedup vs baseline: 1.3094x; 1.3094x over previous
#include <cuda_runtime.h>
#include <cuda_bf16.h>
#include <cstdint>

#define CDIM     64
#define KSLOTS   27
#define TILE     128
#define NMAX     65536
#define EPAD     (KSLOTS * TILE)
#define EMAX     (1572864 + EPAD)
#define MAXSEG   1024

// smem layout for k_conv: rows padded to 144B (ldmatrix conflict-free)
#define SM_XH    0
#define SM_XL    18432
#define SM_WH    36864
#define SM_WL    46080
#define SMEM_TOT 55296

// ---------------- device scratch (static: zero-initialized at load) ----------
__device__ float  g_bufA[(size_t)NMAX * CDIM];   // conv accumulators (fp32)
__device__ uint4  g_xh1[(size_t)NMAX * 8], g_xl1[(size_t)NMAX * 8]; // x split
__device__ uint4  g_xh2[(size_t)NMAX * 8], g_xl2[(size_t)NMAX * 8]; // act split
__device__ uint4  g_w1s[KSLOTS * 1024], g_w2s[KSLOTS * 1024]; // Wt split hi/lo
__device__ int2   g_sij[EMAX];                   // sorted (target, source); pad=(-1,0)
__device__ int    g_hist[KSLOTS];                // invariant: 0 between calls
__device__ int    g_aoff[KSLOTS + 1];
__device__ int    g_cursor[KSLOTS];
__device__ int    g_segoff[MAXSEG + 1];
__device__ double g_s1[MAXSEG], g_s2[MAXSEG];
__device__ float  g_mean[MAXSEG], g_invs[MAXSEG];

// ---------------- helpers -----------------------------------------------------
__device__ __forceinline__ uint32_t smem_u32(const void* p) {
    uint32_t a;
    asm("{ .reg .u64 t; cvta.to.shared.u64 t, %1; cvt.u32.u64 %0, t; }"
        : "=r"(a) : "l"(p));
    return a;
}
__device__ __forceinline__ void cpa16(uint32_t d, const void* s) {
    asm volatile("cp.async.cg.shared.global [%0], [%1], 16;"
                 :: "r"(d), "l"(s) : "memory");
}
#define CPA_COMMIT() asm volatile("cp.async.commit_group;" ::: "memory")
#define CPA_WAIT0()  asm volatile("cp.async.wait_group 0;" ::: "memory")

#define LDMX4(r, addr) \
    asm volatile("ldmatrix.sync.aligned.m8n8.x4.shared.b16 {%0,%1,%2,%3}, [%4];" \
        : "=r"((r)[0]), "=r"((r)[1]), "=r"((r)[2]), "=r"((r)[3]) : "r"(addr))

#define MMA16816(d, a, b0, b1) \
    asm volatile("mma.sync.aligned.m16n8k16.row.col.f32.bf16.bf16.f32 " \
        "{%0,%1,%2,%3}, {%4,%5,%6,%7}, {%8,%9}, {%0,%1,%2,%3};" \
        : "+f"((d)[0]), "+f"((d)[1]), "+f"((d)[2]), "+f"((d)[3]) \
        : "r"((a)[0]), "r"((a)[1]), "r"((a)[2]), "r"((a)[3]), "r"(b0), "r"(b1))

// bf16 hi/lo split of a float pair -> packed u32s
__device__ __forceinline__ void split2(float a, float b, unsigned& h, unsigned& l) {
    __nv_bfloat16 ha = __float2bfloat16_rn(a), hb = __float2bfloat16_rn(b);
    float ra = a - __bfloat162float(ha);
    float rb = b - __bfloat162float(hb);
    __nv_bfloat16 la = __float2bfloat16_rn(ra), lb = __float2bfloat16_rn(rb);
    h = (unsigned)__bfloat16_as_ushort(ha) | ((unsigned)__bfloat16_as_ushort(hb) << 16);
    l = (unsigned)__bfloat16_as_ushort(la) | ((unsigned)__bfloat16_as_ushort(lb) << 16);
}

// ---------------- prep: pad fill + hist + x split + W transpose/split --------
__global__ void k_prep(const int* __restrict__ ek, int E, int fillN,
                       const float* __restrict__ x, int N,
                       const float* __restrict__ W1, const float* __restrict__ W2) {
    __shared__ int h[KSLOTS];
    if (threadIdx.x < KSLOTS) h[threadIdx.x] = 0;
    __syncthreads();
    int stride = gridDim.x * blockDim.x;
    int idx0   = blockIdx.x * blockDim.x + threadIdx.x;

    for (int e = idx0; e < fillN; e += stride) g_sij[e] = make_int2(-1, 0);
    for (int e = idx0; e < E; e += stride) atomicAdd(&h[ek[e]], 1);

    // x rows -> bf16 hi/lo
    for (int p = idx0; p < N; p += stride) {
        const float4* xr = reinterpret_cast<const float4*>(x + (size_t)p * CDIM);
        #pragma unroll
        for (int g = 0; g < 8; g++) {
            float4 a = __ldg(xr + 2 * g), b = __ldg(xr + 2 * g + 1);
            uint4 oh, ol;
            split2(a.x, a.y, oh.x, ol.x);
            split2(a.z, a.w, oh.y, ol.y);
            split2(b.x, b.y, oh.z, ol.z);
            split2(b.z, b.w, oh.w, ol.w);
            g_xh1[(size_t)p * 8 + g] = oh;
            g_xl1[(size_t)p * 8 + g] = ol;
        }
    }

    // W -> transposed Wt[o][c], split hi/lo: per k, 4096 ushort hi then 4096 lo
    int wtot = 2 * KSLOTS * CDIM * CDIM;
    for (int q = idx0; q < wtot; q += stride) {
        int which = (q >= KSLOTS * CDIM * CDIM);
        int rem   = which ? q - KSLOTS * CDIM * CDIM : q;
        int kk = rem >> 12;
        int cc = (rem & 4095) >> 6;
        int oo = rem & 63;
        const float* W = which ? W2 : W1;
        float v = __ldg(W + (size_t)kk * 4096 + cc * 64 + oo);
        __nv_bfloat16 hb = __float2bfloat16_rn(v);
        float r = v - __bfloat162float(hb);
        __nv_bfloat16 lb = __float2bfloat16_rn(r);
        unsigned short* dst = reinterpret_cast<unsigned short*>(which ? g_w2s : g_w1s);
        dst[(size_t)kk * 8192 + oo * 64 + cc]        = __bfloat16_as_ushort(hb);
        dst[(size_t)kk * 8192 + 4096 + oo * 64 + cc] = __bfloat16_as_ushort(lb);
    }

    __syncthreads();
    if (threadIdx.x < KSLOTS) atomicAdd(&g_hist[threadIdx.x], h[threadIdx.x]);
}

__global__ void k_scan(const int* __restrict__ ss, int B, int N) {
    if (threadIdx.x == 0 && blockIdx.x == 0) {
        int off = 0;
        for (int q = 0; q < KSLOTS; q++) {
            g_aoff[q]   = off;
            g_cursor[q] = off;
            off += ((g_hist[q] + TILE - 1) / TILE) * TILE;
        }
        g_aoff[KSLOTS] = off;
        int p = 0;
        for (int b = 0; b < B; b++) { g_segoff[b] = p; p += ss[b]; }
        g_segoff[B] = N;
        for (int b = 0; b < B; b++) { g_s1[b] = 0.0; g_s2[b] = 0.0; }
    }
}

// block-aggregated counting-sort scatter: 1 global atomic per (block, slot)
__global__ void k_scatter(const int* __restrict__ i, const int* __restrict__ j,
                          const int* __restrict__ k, int E) {
    __shared__ int sh[KSLOTS], sbase[KSLOTS];
    int tid = threadIdx.x;
    if (tid < KSLOTS) sh[tid] = 0;
    __syncthreads();
    int e = blockIdx.x * blockDim.x + tid;
    int kk = 0, rank = 0;
    bool valid = (e < E);
    if (valid) {
        kk   = k[e];
        rank = atomicAdd(&sh[kk], 1);
    }
    __syncthreads();
    if (tid < KSLOTS && sh[tid] > 0)
        sbase[tid] = atomicAdd(&g_cursor[tid], sh[tid]);
    __syncthreads();
    if (valid) {
        int pos = sbase[kk] + rank;
        g_sij[pos] = make_int2(i[e], j[e]);
    }
    if (blockIdx.x == 0 && tid < KSLOTS) g_hist[tid] = 0;   // reset for replay
}

// ---------------- tensor-core conv (mma.sync bf16 split, 3-term) -------------
// Tile = 128 edges x 64 outputs. Warp w: edges [32w,32w+32) x all 64 outputs.
// cp.async staging; lane-pair shuffle assembles float4 REDs from fragments.
__global__ void __launch_bounds__(128)
k_conv(const uint4* __restrict__ gXh, const uint4* __restrict__ gXl,
       const uint4* __restrict__ gW, float* __restrict__ out) {
    extern __shared__ char smem[];
    int tb = blockIdx.x * TILE;
    if (tb >= g_aoff[KSLOTS]) return;
    int kk = 0;
    while (g_aoff[kk + 1] <= tb) kk++;

    int tid = threadIdx.x, w = tid >> 5, lane = tid & 31;
    uint32_t sb = smem_u32(smem);

    // stage Wt[k] hi/lo (rows o, stride 144B) via cp.async
    const uint4* ws = gW + (size_t)kk * 1024;
    #pragma unroll
    for (int q = 0; q < 4; q++) {
        int idx = tid + 128 * q;
        int o = idx >> 3, c8 = idx & 7;
        cpa16(sb + SM_WH + o * 144 + c8 * 16, ws + idx);
        cpa16(sb + SM_WL + o * 144 + c8 * 16, ws + 512 + idx);
    }
    // gather edge rows (128B hi + lo, stride 144B) via cp.async
    int2 ij = g_sij[tb + tid];
    const uint4* xh = gXh + (size_t)ij.y * 8;
    const uint4* xl = gXl + (size_t)ij.y * 8;
    #pragma unroll
    for (int q = 0; q < 8; q++) {
        cpa16(sb + SM_XH + tid * 144 + q * 16, xh + q);
        cpa16(sb + SM_XL + tid * 144 + q * 16, xl + q);
    }
    CPA_COMMIT();
    CPA_WAIT0();
    __syncthreads();

    float acc[2][8][4];
    #pragma unroll
    for (int a = 0; a < 2; a++)
        #pragma unroll
        for (int b = 0; b < 8; b++)
            #pragma unroll
            for (int c = 0; c < 4; c++) acc[a][b][c] = 0.f;

    // per-lane ldmatrix base addresses
    uint32_t aH[2], aL[2], bH[4], bL[4];
    {
        int arow  = lane & 15;
        int abyte = (lane >> 4) * 16;          // k-half select
        #pragma unroll
        for (int mt = 0; mt < 2; mt++) {
            int row = w * 32 + mt * 16 + arow;
            aH[mt] = sb + SM_XH + row * 144 + abyte;
            aL[mt] = sb + SM_XL + row * 144 + abyte;
        }
        int nsub  = (lane & 7) + 8 * (lane >> 4);   // n within 16-octet pair
        int kbyte = ((lane >> 3) & 1) * 16;         // k-half select
        #pragma unroll
        for (int np = 0; np < 4; np++) {
            int nn = np * 16 + nsub;
            bH[np] = sb + SM_WH + nn * 144 + kbyte;
            bL[np] = sb + SM_WL + nn * 144 + kbyte;
        }
    }

    #pragma unroll
    for (int ks = 0; ks < 4; ks++) {
        uint32_t ah[2][4], al[2][4];
        #pragma unroll
        for (int mt = 0; mt < 2; mt++) {
            LDMX4(ah[mt], aH[mt] + ks * 32);
            LDMX4(al[mt], aL[mt] + ks * 32);
        }
        #pragma unroll
        for (int np = 0; np < 4; np++) {
            uint32_t bh[4], bl[4];
            LDMX4(bh, bH[np] + ks * 32);
            LDMX4(bl, bL[np] + ks * 32);
            #pragma unroll
            for (int mt = 0; mt < 2; mt++) {
                float* d0 = acc[mt][2 * np];
                float* d1 = acc[mt][2 * np + 1];
                MMA16816(d0, ah[mt], bh[0], bh[1]);
                MMA16816(d0, al[mt], bh[0], bh[1]);
                MMA16816(d0, ah[mt], bl[0], bl[1]);
                MMA16816(d1, ah[mt], bh[2], bh[3]);
                MMA16816(d1, al[mt], bh[2], bh[3]);
                MMA16816(d1, ah[mt], bl[2], bl[3]);
            }
        }
    }

    // scatter: lane-pair shuffle assembles float4 REDs
    // even lane -> row r (own d0,d1 + partner's d0,d1 as cols +2,+3)
    // odd lane  -> row r+8 (partner's d2,d3 as cols +0,+1 + own d2,d3)
    int odd   = lane & 1;
    int cbase = 4 * ((lane & 3) >> 1);
    #pragma unroll
    for (int mt = 0; mt < 2; mt++) {
        int row = w * 32 + mt * 16 + (lane >> 2) + odd * 8;
        int ii  = g_sij[tb + row].x;
        float* orow = out + (size_t)(ii < 0 ? 0 : ii) * CDIM;
        #pragma unroll
        for (int nt = 0; nt < 8; nt++) {
            float d0 = acc[mt][nt][0], d1 = acc[mt][nt][1];
            float d2 = acc[mt][nt][2], d3 = acc[mt][nt][3];
            float gx = odd ? d0 : d2, gy = odd ? d1 : d3;
            gx = __shfl_xor_sync(0xffffffffu, gx, 1);
            gy = __shfl_xor_sync(0xffffffffu, gy, 1);
            float4 v = odd ? make_float4(gx, gy, d2, d3)
                           : make_float4(d0, d1, gx, gy);
            if (ii >= 0)
                atomicAdd(reinterpret_cast<float4*>(orow + nt * 8 + cbase), v);
        }
    }
}

// ---------------- ragged LayerNorm ------------------------------------------
__global__ void k_stats(const float* __restrict__ v) {
    int seg = blockIdx.x;
    long long e0 = (long long)g_segoff[seg] * CDIM;
    long long e1 = (long long)g_segoff[seg + 1] * CDIM;
    double s1 = 0.0, s2 = 0.0;
    long long stride = (long long)gridDim.y * blockDim.x;
    for (long long idx = e0 + (long long)blockIdx.y * blockDim.x + threadIdx.x;
         idx < e1; idx += stride) {
        double d = (double)v[idx];
        s1 += d;
        s2 += d * d;
    }
    #pragma unroll
    for (int o = 16; o; o >>= 1) {
        s1 += __shfl_down_sync(0xffffffffu, s1, o);
        s2 += __shfl_down_sync(0xffffffffu, s2, o);
    }
    __shared__ double w1[8], w2[8];
    int wid = threadIdx.x >> 5, lid = threadIdx.x & 31;
    if (lid == 0) { w1[wid] = s1; w2[wid] = s2; }
    __syncthreads();
    if (threadIdx.x == 0) {
        double a = 0.0, b = 0.0;
        int nw = blockDim.x >> 5;
        for (int q = 0; q < nw; q++) { a += w1[q]; b += w2[q]; }
        atomicAdd(&g_s1[seg], a);
        atomicAdd(&g_s2[seg], b);
    }
}

__global__ void k_finalize(int B) {
    int s = blockIdx.x * blockDim.x + threadIdx.x;
    if (s < B) {
        double cnt  = (double)(g_segoff[s + 1] - g_segoff[s]) * (double)CDIM;
        double mean = g_s1[s] / cnt;
        double var  = g_s2[s] / cnt - mean * mean;
        g_mean[s] = (float)mean;
        g_invs[s] = rsqrtf((float)var + 1e-5f);
    }
}

__device__ __forceinline__ int find_seg(int p, int B) {
    int s = 0;
    #pragma unroll 1
    while (s + 1 < B && __ldg(&g_segoff[s + 1]) <= p) s++;
    return s;
}

// LN1 + relu -> bf16 hi/lo split; re-zeroes accumulator + layer-2 stats
__global__ void k_norm_relu(float* __restrict__ v,
                            const float* __restrict__ gamma,
                            const float* __restrict__ beta,
                            uint4* __restrict__ oh, uint4* __restrict__ ol,
                            int N, int B) {
    if (blockIdx.x == 0 && threadIdx.x < B) {
        g_s1[threadIdx.x] = 0.0;
        g_s2[threadIdx.x] = 0.0;
    }
    int total = N * (CDIM / 4);
    float4 z = make_float4(0.f, 0.f, 0.f, 0.f);
    for (int q = blockIdx.x * blockDim.x + threadIdx.x; q < total;
         q += gridDim.x * blockDim.x) {
        int p  = q >> 4;
        int c4 = (q & 15) << 2;
        int s  = find_seg(p, B);
        float mu = g_mean[s], inv = g_invs[s];
        float4 x4 = reinterpret_cast<float4*>(v)[q];
        reinterpret_cast<float4*>(v)[q] = z;   // re-zero for conv2
        float4 gg = __ldg(reinterpret_cast<const float4*>(gamma + c4));
        float4 bb = __ldg(reinterpret_cast<const float4*>(beta + c4));
        float r0 = fmaxf(fmaf((x4.x - mu) * inv, gg.x, bb.x), 0.f);
        float r1 = fmaxf(fmaf((x4.y - mu) * inv, gg.y, bb.y), 0.f);
        float r2 = fmaxf(fmaf((x4.z - mu) * inv, gg.z, bb.z), 0.f);
        float r3 = fmaxf(fmaf((x4.w - mu) * inv, gg.w, bb.w), 0.f);
        uint2 hh, ll;
        split2(r0, r1, hh.x, ll.x);
        split2(r2, r3, hh.y, ll.y);
        reinterpret_cast<uint2*>(oh)[(size_t)p * 16 + (q & 15)] = hh;
        reinterpret_cast<uint2*>(ol)[(size_t)p * 16 + (q & 15)] = ll;
    }
}

// LN2 + residual + relu; re-zeroes accumulator for the next replay
__global__ void k_norm_res_relu(float* __restrict__ v,
                                const float* __restrict__ gamma,
                                const float* __restrict__ beta,
                                const float* __restrict__ xin,
                                float* __restrict__ o, int N, int B) {
    int total = N * (CDIM / 4);
    float4 z = make_float4(0.f, 0.f, 0.f, 0.f);
    for (int q = blockIdx.x * blockDim.x + threadIdx.x; q < total;
         q += gridDim.x * blockDim.x) {
        int p  = q >> 4;
        int c4 = (q & 15) << 2;
        int s  = find_seg(p, B);
        float mu = g_mean[s], inv = g_invs[s];
        float4 x4 = reinterpret_cast<float4*>(v)[q];
        reinterpret_cast<float4*>(v)[q] = z;   // re-zero for next call
        float4 rx = __ldg(reinterpret_cast<const float4*>(xin) + q);
        float4 gg = __ldg(reinterpret_cast<const float4*>(gamma + c4));
        float4 bb = __ldg(reinterpret_cast<const float4*>(beta + c4));
        float4 r;
        r.x = fmaxf(fmaf((x4.x - mu) * inv, gg.x, bb.x) + rx.x, 0.f);
        r.y = fmaxf(fmaf((x4.y - mu) * inv, gg.y, bb.y) + rx.y, 0.f);
        r.z = fmaxf(fmaf((x4.z - mu) * inv, gg.z, bb.z) + rx.z, 0.f);
        r.w = fmaxf(fmaf((x4.w - mu) * inv, gg.w, bb.w) + rx.w, 0.f);
        reinterpret_cast<float4*>(o)[q] = r;
    }
}

// ---------------- host-side launch sequence ---------------------------------
extern "C" void kernel_launch(void* const* d_in, const int* in_sizes, int n_in,
                              void* d_out, int out_size) {
    (void)n_in; (void)out_size;
    const float* x  = (const float*)d_in[0];
    const float* W1 = (const float*)d_in[1];
    const float* g1 = (const float*)d_in[2];
    const float* b1 = (const float*)d_in[3];
    const float* W2 = (const float*)d_in[4];
    const float* g2 = (const float*)d_in[5];
    const float* b2 = (const float*)d_in[6];
    const int*   ei = (const int*)d_in[7];
    const int*   ej = (const int*)d_in[8];
    const int*   ek = (const int*)d_in[9];
    const int*   ss = (const int*)d_in[10];

    int N = in_sizes[0] / CDIM;
    int E = in_sizes[7];
    int B = in_sizes[10];
    float* out = (float*)d_out;

    float* pA; cudaGetSymbolAddress((void**)&pA, g_bufA);
    uint4 *xh1, *xl1, *xh2, *xl2, *w1s, *w2s;
    cudaGetSymbolAddress((void**)&xh1, g_xh1);
    cudaGetSymbolAddress((void**)&xl1, g_xl1);
    cudaGetSymbolAddress((void**)&xh2, g_xh2);
    cudaGetSymbolAddress((void**)&xl2, g_xl2);
    cudaGetSymbolAddress((void**)&w1s, g_w1s);
    cudaGetSymbolAddress((void**)&w2s, g_w2s);

    cudaFuncSetAttribute(k_conv, cudaFuncAttributeMaxDynamicSharedMemorySize, SMEM_TOT);

    int fillN = E + EPAD; if (fillN > EMAX) fillN = EMAX;
    int statB = (B + 31) / 32;
    int sgrid = (E + 255) / 256;
    int nb    = (E + KSLOTS * (TILE - 1) + TILE - 1) / TILE;

    // replay-state invariants: g_hist=0 (end of k_scatter), g_bufA=0 (LN epilogues)
    k_prep<<<1024, 256>>>(ek, E, fillN, x, N, W1, W2);            // L1
    k_scan<<<1, 1>>>(ss, B, N);                                    // L2
    k_scatter<<<sgrid, 256>>>(ei, ej, ek, E);                      // L3

    k_conv<<<nb, 128, SMEM_TOT>>>(xh1, xl1, w1s, pA);              // L4 (profiled)
    k_stats<<<dim3(B, 128), 256>>>(pA);                            // L5
    k_finalize<<<statB, 32>>>(B);                                  // L6
    k_norm_relu<<<512, 256>>>(pA, g1, b1, xh2, xl2, N, B);         // L7

    k_conv<<<nb, 128, SMEM_TOT>>>(xh2, xl2, w2s, pA);              // L8
    k_stats<<<dim3(B, 128), 256>>>(pA);                            // L9
    k_finalize<<<statB, 32>>>(B);                                  // L10
    k_norm_res_relu<<<512, 256>>>(pA, g2, b2, x, out, N, B);       // L11
}

// round 11
// speedup vs baseline: 1.6247x; 1.2407x over previous
#include <cuda_runtime.h>
#include <cuda_bf16.h>
#include <cstdint>

#define CDIM     64
#define KSLOTS   27
#define TILE     128
#define NMAX     65536
#define EPAD     (KSLOTS * TILE)
#define EMAX     (1572864 + EPAD)
#define MAXSEG   1024

// smem layout for k_conv: rows padded to 144B (ldmatrix conflict-free)
#define SM_XH    0
#define SM_XL    18432
#define SM_WH    36864
#define SM_WL    46080
#define SMEM_TOT 55296

// ---------------- device scratch (static: zero-initialized at load) ----------
__device__ float  g_bufA[(size_t)NMAX * CDIM];   // conv accumulators (fp32)
__device__ uint4  g_xh1[(size_t)NMAX * 8], g_xl1[(size_t)NMAX * 8]; // x split
__device__ uint4  g_xh2[(size_t)NMAX * 8], g_xl2[(size_t)NMAX * 8]; // act split
__device__ uint4  g_w1s[KSLOTS * 1024], g_w2s[KSLOTS * 1024]; // Wt split hi/lo
__device__ int2   g_sij[EMAX];                   // sorted (target, source); pad=(-1,0)
__device__ int    g_hist[KSLOTS];                // invariant: 0 between calls
__device__ int    g_aoff[KSLOTS + 1];
__device__ int    g_cursor[KSLOTS];
__device__ int    g_segoff[MAXSEG + 1];
__device__ double g_s1[MAXSEG], g_s2[MAXSEG];
__device__ float  g_mean[MAXSEG], g_invs[MAXSEG];

// ---------------- helpers -----------------------------------------------------
__device__ __forceinline__ uint32_t smem_u32(const void* p) {
    uint32_t a;
    asm("{ .reg .u64 t; cvta.to.shared.u64 t, %1; cvt.u32.u64 %0, t; }"
        : "=r"(a) : "l"(p));
    return a;
}
__device__ __forceinline__ void cpa16(uint32_t d, const void* s) {
    asm volatile("cp.async.cg.shared.global [%0], [%1], 16;"
                 :: "r"(d), "l"(s) : "memory");
}
#define CPA_COMMIT() asm volatile("cp.async.commit_group;" ::: "memory")
#define CPA_WAIT0()  asm volatile("cp.async.wait_group 0;" ::: "memory")

#define LDMX4(r, addr) \
    asm volatile("ldmatrix.sync.aligned.m8n8.x4.shared.b16 {%0,%1,%2,%3}, [%4];" \
        : "=r"((r)[0]), "=r"((r)[1]), "=r"((r)[2]), "=r"((r)[3]) : "r"(addr))

#define MMA16816(d, a, b0, b1) \
    asm volatile("mma.sync.aligned.m16n8k16.row.col.f32.bf16.bf16.f32 " \
        "{%0,%1,%2,%3}, {%4,%5,%6,%7}, {%8,%9}, {%0,%1,%2,%3};" \
        : "+f"((d)[0]), "+f"((d)[1]), "+f"((d)[2]), "+f"((d)[3]) \
        : "r"((a)[0]), "r"((a)[1]), "r"((a)[2]), "r"((a)[3]), "r"(b0), "r"(b1))

// bf16 hi/lo split of a float pair -> packed u32s
__device__ __forceinline__ void split2(float a, float b, unsigned& h, unsigned& l) {
    __nv_bfloat16 ha = __float2bfloat16_rn(a), hb = __float2bfloat16_rn(b);
    float ra = a - __bfloat162float(ha);
    float rb = b - __bfloat162float(hb);
    __nv_bfloat16 la = __float2bfloat16_rn(ra), lb = __float2bfloat16_rn(rb);
    h = (unsigned)__bfloat16_as_ushort(ha) | ((unsigned)__bfloat16_as_ushort(hb) << 16);
    l = (unsigned)__bfloat16_as_ushort(la) | ((unsigned)__bfloat16_as_ushort(lb) << 16);
}

// ---------------- prep: pad fill + hist + x split + W transpose/split --------
__global__ void k_prep(const int* __restrict__ ek, int E, int fillN,
                       const float* __restrict__ x, int N,
                       const float* __restrict__ W1, const float* __restrict__ W2) {
    __shared__ int h[KSLOTS];
    if (threadIdx.x < KSLOTS) h[threadIdx.x] = 0;
    __syncthreads();
    int stride = gridDim.x * blockDim.x;
    int idx0   = blockIdx.x * blockDim.x + threadIdx.x;

    for (int e = idx0; e < fillN; e += stride) g_sij[e] = make_int2(-1, 0);
    for (int e = idx0; e < E; e += stride) atomicAdd(&h[ek[e]], 1);

    // x rows -> bf16 hi/lo
    for (int p = idx0; p < N; p += stride) {
        const float4* xr = reinterpret_cast<const float4*>(x + (size_t)p * CDIM);
        #pragma unroll
        for (int g = 0; g < 8; g++) {
            float4 a = __ldg(xr + 2 * g), b = __ldg(xr + 2 * g + 1);
            uint4 oh, ol;
            split2(a.x, a.y, oh.x, ol.x);
            split2(a.z, a.w, oh.y, ol.y);
            split2(b.x, b.y, oh.z, ol.z);
            split2(b.z, b.w, oh.w, ol.w);
            g_xh1[(size_t)p * 8 + g] = oh;
            g_xl1[(size_t)p * 8 + g] = ol;
        }
    }

    // W -> transposed Wt[o][c], split hi/lo: per k, 4096 ushort hi then 4096 lo
    int wtot = 2 * KSLOTS * CDIM * CDIM;
    for (int q = idx0; q < wtot; q += stride) {
        int which = (q >= KSLOTS * CDIM * CDIM);
        int rem   = which ? q - KSLOTS * CDIM * CDIM : q;
        int kk = rem >> 12;
        int cc = (rem & 4095) >> 6;
        int oo = rem & 63;
        const float* W = which ? W2 : W1;
        float v = __ldg(W + (size_t)kk * 4096 + cc * 64 + oo);
        __nv_bfloat16 hb = __float2bfloat16_rn(v);
        float r = v - __bfloat162float(hb);
        __nv_bfloat16 lb = __float2bfloat16_rn(r);
        unsigned short* dst = reinterpret_cast<unsigned short*>(which ? g_w2s : g_w1s);
        dst[(size_t)kk * 8192 + oo * 64 + cc]        = __bfloat16_as_ushort(hb);
        dst[(size_t)kk * 8192 + 4096 + oo * 64 + cc] = __bfloat16_as_ushort(lb);
    }

    __syncthreads();
    if (threadIdx.x < KSLOTS) atomicAdd(&g_hist[threadIdx.x], h[threadIdx.x]);
}

__global__ void k_scan(const int* __restrict__ ss, int B, int N) {
    if (threadIdx.x == 0 && blockIdx.x == 0) {
        int off = 0;
        for (int q = 0; q < KSLOTS; q++) {
            g_aoff[q]   = off;
            g_cursor[q] = off;
            off += ((g_hist[q] + TILE - 1) / TILE) * TILE;
        }
        g_aoff[KSLOTS] = off;
        int p = 0;
        for (int b = 0; b < B; b++) { g_segoff[b] = p; p += ss[b]; }
        g_segoff[B] = N;
        for (int b = 0; b < B; b++) { g_s1[b] = 0.0; g_s2[b] = 0.0; }
    }
}

// block-aggregated counting-sort scatter: 1 global atomic per (block, slot)
__global__ void k_scatter(const int* __restrict__ i, const int* __restrict__ j,
                          const int* __restrict__ k, int E) {
    __shared__ int sh[KSLOTS], sbase[KSLOTS];
    int tid = threadIdx.x;
    if (tid < KSLOTS) sh[tid] = 0;
    __syncthreads();
    int e = blockIdx.x * blockDim.x + tid;
    int kk = 0, rank = 0;
    bool valid = (e < E);
    if (valid) {
        kk   = k[e];
        rank = atomicAdd(&sh[kk], 1);
    }
    __syncthreads();
    if (tid < KSLOTS && sh[tid] > 0)
        sbase[tid] = atomicAdd(&g_cursor[tid], sh[tid]);
    __syncthreads();
    if (valid) {
        int pos = sbase[kk] + rank;
        g_sij[pos] = make_int2(i[e], j[e]);
    }
    if (blockIdx.x == 0 && tid < KSLOTS) g_hist[tid] = 0;   // reset for replay
}

// ---------------- tensor-core conv (mma.sync bf16 split, 3-term) -------------
// Tile = 128 edges x 64 outputs. Warp w: edges [32w,32w+32) x all 64 outputs.
// Coalesced cp.async gather: 8 lanes cooperatively load one row's 128B, so
// each warp instruction touches 4 fully-used 128B lines (was 32 partial).
__global__ void __launch_bounds__(128)
k_conv(const uint4* __restrict__ gXh, const uint4* __restrict__ gXl,
       const uint4* __restrict__ gW, float* __restrict__ out) {
    extern __shared__ char smem[];
    int tb = blockIdx.x * TILE;
    if (tb >= g_aoff[KSLOTS]) return;
    int kk = 0;
    while (g_aoff[kk + 1] <= tb) kk++;

    int tid = threadIdx.x, w = tid >> 5, lane = tid & 31;
    uint32_t sb = smem_u32(smem);

    // stage Wt[k] hi/lo (rows o, stride 144B) via cp.async (coalesced)
    const uint4* ws = gW + (size_t)kk * 1024;
    #pragma unroll
    for (int q = 0; q < 4; q++) {
        int idx = tid + 128 * q;
        int o = idx >> 3, c8 = idx & 7;
        cpa16(sb + SM_WH + o * 144 + c8 * 16, ws + idx);
        cpa16(sb + SM_WL + o * 144 + c8 * 16, ws + 512 + idx);
    }
    // coalesced gather: row = idx>>3, chunk = idx&7; 8 lanes cover one row
    #pragma unroll
    for (int q = 0; q < 8; q++) {
        int idx = tid + 128 * q;
        int row = idx >> 3, ch = idx & 7;
        int jj  = g_sij[tb + row].y;          // 8-lane broadcast load
        cpa16(sb + SM_XH + row * 144 + ch * 16, gXh + (size_t)jj * 8 + ch);
        cpa16(sb + SM_XL + row * 144 + ch * 16, gXl + (size_t)jj * 8 + ch);
    }
    CPA_COMMIT();
    CPA_WAIT0();
    __syncthreads();

    float acc[2][8][4];
    #pragma unroll
    for (int a = 0; a < 2; a++)
        #pragma unroll
        for (int b = 0; b < 8; b++)
            #pragma unroll
            for (int c = 0; c < 4; c++) acc[a][b][c] = 0.f;

    // per-lane ldmatrix base addresses
    uint32_t aH[2], aL[2], bH[4], bL[4];
    {
        int arow  = lane & 15;
        int abyte = (lane >> 4) * 16;          // k-half select
        #pragma unroll
        for (int mt = 0; mt < 2; mt++) {
            int row = w * 32 + mt * 16 + arow;
            aH[mt] = sb + SM_XH + row * 144 + abyte;
            aL[mt] = sb + SM_XL + row * 144 + abyte;
        }
        int nsub  = (lane & 7) + 8 * (lane >> 4);   // n within 16-octet pair
        int kbyte = ((lane >> 3) & 1) * 16;         // k-half select
        #pragma unroll
        for (int np = 0; np < 4; np++) {
            int nn = np * 16 + nsub;
            bH[np] = sb + SM_WH + nn * 144 + kbyte;
            bL[np] = sb + SM_WL + nn * 144 + kbyte;
        }
    }

    #pragma unroll
    for (int ks = 0; ks < 4; ks++) {
        uint32_t ah[2][4], al[2][4];
        #pragma unroll
        for (int mt = 0; mt < 2; mt++) {
            LDMX4(ah[mt], aH[mt] + ks * 32);
            LDMX4(al[mt], aL[mt] + ks * 32);
        }
        #pragma unroll
        for (int np = 0; np < 4; np++) {
            uint32_t bh[4], bl[4];
            LDMX4(bh, bH[np] + ks * 32);
            LDMX4(bl, bL[np] + ks * 32);
            #pragma unroll
            for (int mt = 0; mt < 2; mt++) {
                float* d0 = acc[mt][2 * np];
                float* d1 = acc[mt][2 * np + 1];
                MMA16816(d0, ah[mt], bh[0], bh[1]);
                MMA16816(d0, al[mt], bh[0], bh[1]);
                MMA16816(d0, ah[mt], bl[0], bl[1]);
                MMA16816(d1, ah[mt], bh[2], bh[3]);
                MMA16816(d1, al[mt], bh[2], bh[3]);
                MMA16816(d1, ah[mt], bl[2], bl[3]);
            }
        }
    }

    // scatter: lane-pair shuffle assembles float4 REDs
    int odd   = lane & 1;
    int cbase = 4 * ((lane & 3) >> 1);
    #pragma unroll
    for (int mt = 0; mt < 2; mt++) {
        int row = w * 32 + mt * 16 + (lane >> 2) + odd * 8;
        int ii  = g_sij[tb + row].x;
        float* orow = out + (size_t)(ii < 0 ? 0 : ii) * CDIM;
        #pragma unroll
        for (int nt = 0; nt < 8; nt++) {
            float d0 = acc[mt][nt][0], d1 = acc[mt][nt][1];
            float d2 = acc[mt][nt][2], d3 = acc[mt][nt][3];
            float gx = odd ? d0 : d2, gy = odd ? d1 : d3;
            gx = __shfl_xor_sync(0xffffffffu, gx, 1);
            gy = __shfl_xor_sync(0xffffffffu, gy, 1);
            float4 v = odd ? make_float4(gx, gy, d2, d3)
                           : make_float4(d0, d1, gx, gy);
            if (ii >= 0)
                atomicAdd(reinterpret_cast<float4*>(orow + nt * 8 + cbase), v);
        }
    }
}

// ---------------- ragged LayerNorm ------------------------------------------
__global__ void k_stats(const float* __restrict__ v) {
    int seg = blockIdx.x;
    long long e0 = (long long)g_segoff[seg] * CDIM;
    long long e1 = (long long)g_segoff[seg + 1] * CDIM;
    double s1 = 0.0, s2 = 0.0;
    long long stride = (long long)gridDim.y * blockDim.x;
    for (long long idx = e0 + (long long)blockIdx.y * blockDim.x + threadIdx.x;
         idx < e1; idx += stride) {
        double d = (double)v[idx];
        s1 += d;
        s2 += d * d;
    }
    #pragma unroll
    for (int o = 16; o; o >>= 1) {
        s1 += __shfl_down_sync(0xffffffffu, s1, o);
        s2 += __shfl_down_sync(0xffffffffu, s2, o);
    }
    __shared__ double w1[8], w2[8];
    int wid = threadIdx.x >> 5, lid = threadIdx.x & 31;
    if (lid == 0) { w1[wid] = s1; w2[wid] = s2; }
    __syncthreads();
    if (threadIdx.x == 0) {
        double a = 0.0, b = 0.0;
        int nw = blockDim.x >> 5;
        for (int q = 0; q < nw; q++) { a += w1[q]; b += w2[q]; }
        atomicAdd(&g_s1[seg], a);
        atomicAdd(&g_s2[seg], b);
    }
}

__global__ void k_finalize(int B) {
    int s = blockIdx.x * blockDim.x + threadIdx.x;
    if (s < B) {
        double cnt  = (double)(g_segoff[s + 1] - g_segoff[s]) * (double)CDIM;
        double mean = g_s1[s] / cnt;
        double var  = g_s2[s] / cnt - mean * mean;
        g_mean[s] = (float)mean;
        g_invs[s] = rsqrtf((float)var + 1e-5f);
    }
}

__device__ __forceinline__ int find_seg(int p, int B) {
    int s = 0;
    #pragma unroll 1
    while (s + 1 < B && __ldg(&g_segoff[s + 1]) <= p) s++;
    return s;
}

// LN1 + relu -> bf16 hi/lo split; re-zeroes accumulator + layer-2 stats
__global__ void k_norm_relu(float* __restrict__ v,
                            const float* __restrict__ gamma,
                            const float* __restrict__ beta,
                            uint4* __restrict__ oh, uint4* __restrict__ ol,
                            int N, int B) {
    if (blockIdx.x == 0 && threadIdx.x < B) {
        g_s1[threadIdx.x] = 0.0;
        g_s2[threadIdx.x] = 0.0;
    }
    int total = N * (CDIM / 4);
    float4 z = make_float4(0.f, 0.f, 0.f, 0.f);
    for (int q = blockIdx.x * blockDim.x + threadIdx.x; q < total;
         q += gridDim.x * blockDim.x) {
        int p  = q >> 4;
        int c4 = (q & 15) << 2;
        int s  = find_seg(p, B);
        float mu = g_mean[s], inv = g_invs[s];
        float4 x4 = reinterpret_cast<float4*>(v)[q];
        reinterpret_cast<float4*>(v)[q] = z;   // re-zero for conv2
        float4 gg = __ldg(reinterpret_cast<const float4*>(gamma + c4));
        float4 bb = __ldg(reinterpret_cast<const float4*>(beta + c4));
        float r0 = fmaxf(fmaf((x4.x - mu) * inv, gg.x, bb.x), 0.f);
        float r1 = fmaxf(fmaf((x4.y - mu) * inv, gg.y, bb.y), 0.f);
        float r2 = fmaxf(fmaf((x4.z - mu) * inv, gg.z, bb.z), 0.f);
        float r3 = fmaxf(fmaf((x4.w - mu) * inv, gg.w, bb.w), 0.f);
        uint2 hh, ll;
        split2(r0, r1, hh.x, ll.x);
        split2(r2, r3, hh.y, ll.y);
        reinterpret_cast<uint2*>(oh)[(size_t)p * 16 + (q & 15)] = hh;
        reinterpret_cast<uint2*>(ol)[(size_t)p * 16 + (q & 15)] = ll;
    }
}

// LN2 + residual + relu; re-zeroes accumulator for the next replay
__global__ void k_norm_res_relu(float* __restrict__ v,
                                const float* __restrict__ gamma,
                                const float* __restrict__ beta,
                                const float* __restrict__ xin,
                                float* __restrict__ o, int N, int B) {
    int total = N * (CDIM / 4);
    float4 z = make_float4(0.f, 0.f, 0.f, 0.f);
    for (int q = blockIdx.x * blockDim.x + threadIdx.x; q < total;
         q += gridDim.x * blockDim.x) {
        int p  = q >> 4;
        int c4 = (q & 15) << 2;
        int s  = find_seg(p, B);
        float mu = g_mean[s], inv = g_invs[s];
        float4 x4 = reinterpret_cast<float4*>(v)[q];
        reinterpret_cast<float4*>(v)[q] = z;   // re-zero for next call
        float4 rx = __ldg(reinterpret_cast<const float4*>(xin) + q);
        float4 gg = __ldg(reinterpret_cast<const float4*>(gamma + c4));
        float4 bb = __ldg(reinterpret_cast<const float4*>(beta + c4));
        float4 r;
        r.x = fmaxf(fmaf((x4.x - mu) * inv, gg.x, bb.x) + rx.x, 0.f);
        r.y = fmaxf(fmaf((x4.y - mu) * inv, gg.y, bb.y) + rx.y, 0.f);
        r.z = fmaxf(fmaf((x4.z - mu) * inv, gg.z, bb.z) + rx.z, 0.f);
        r.w = fmaxf(fmaf((x4.w - mu) * inv, gg.w, bb.w) + rx.w, 0.f);
        reinterpret_cast<float4*>(o)[q] = r;
    }
}

// ---------------- host-side launch sequence ---------------------------------
extern "C" void kernel_launch(void* const* d_in, const int* in_sizes, int n_in,
                              void* d_out, int out_size) {
    (void)n_in; (void)out_size;
    const float* x  = (const float*)d_in[0];
    const float* W1 = (const float*)d_in[1];
    const float* g1 = (const float*)d_in[2];
    const float* b1 = (const float*)d_in[3];
    const float* W2 = (const float*)d_in[4];
    const float* g2 = (const float*)d_in[5];
    const float* b2 = (const float*)d_in[6];
    const int*   ei = (const int*)d_in[7];
    const int*   ej = (const int*)d_in[8];
    const int*   ek = (const int*)d_in[9];
    const int*   ss = (const int*)d_in[10];

    int N = in_sizes[0] / CDIM;
    int E = in_sizes[7];
    int B = in_sizes[10];
    float* out = (float*)d_out;

    float* pA; cudaGetSymbolAddress((void**)&pA, g_bufA);
    uint4 *xh1, *xl1, *xh2, *xl2, *w1s, *w2s;
    cudaGetSymbolAddress((void**)&xh1, g_xh1);
    cudaGetSymbolAddress((void**)&xl1, g_xl1);
    cudaGetSymbolAddress((void**)&xh2, g_xh2);
    cudaGetSymbolAddress((void**)&xl2, g_xl2);
    cudaGetSymbolAddress((void**)&w1s, g_w1s);
    cudaGetSymbolAddress((void**)&w2s, g_w2s);

    cudaFuncSetAttribute(k_conv, cudaFuncAttributeMaxDynamicSharedMemorySize, SMEM_TOT);

    int fillN = E + EPAD; if (fillN > EMAX) fillN = EMAX;
    int statB = (B + 31) / 32;
    int sgrid = (E + 255) / 256;
    int nb    = (E + KSLOTS * (TILE - 1) + TILE - 1) / TILE;

    // replay-state invariants: g_hist=0 (end of k_scatter), g_bufA=0 (LN epilogues)
    k_prep<<<1024, 256>>>(ek, E, fillN, x, N, W1, W2);            // L1
    k_scan<<<1, 1>>>(ss, B, N);                                    // L2
    k_scatter<<<sgrid, 256>>>(ei, ej, ek, E);                      // L3

    k_conv<<<nb, 128, SMEM_TOT>>>(xh1, xl1, w1s, pA);              // L4 (profiled)
    k_stats<<<dim3(B, 128), 256>>>(pA);                            // L5
    k_finalize<<<statB, 32>>>(B);                                  // L6
    k_norm_relu<<<512, 256>>>(pA, g1, b1, xh2, xl2, N, B);         // L7

    k_conv<<<nb, 128, SMEM_TOT>>>(xh2, xl2, w2s, pA);              // L8
    k_stats<<<dim3(B, 128), 256>>>(pA);                            // L9
    k_finalize<<<statB, 32>>>(B);                                  // L10
    k_norm_res_relu<<<512, 256>>>(pA, g2, b2, x, out, N, B);       // L11
}

// round 12
// speedup vs baseline: 1.8833x; 1.1592x over previous
#include <cuda_runtime.h>
#include <cuda_fp16.h>
#include <cstdint>

#define CDIM     64
#define KSLOTS   27
#define TILE     128
#define NMAX     65536
#define EPAD     (KSLOTS * TILE)
#define EMAX     (1572864 + EPAD)
#define MAXSEG   1024

// smem layout for k_conv: rows padded to 144B (ldmatrix conflict-free)
// X region (0..36863) is reused as the D transpose buffer (128 x 272B).
#define SM_XH    0
#define SM_XL    18432
#define SM_WH    36864
#define SMEM_TOT 46080
#define DSTRIDE  68            // D row stride in floats (272B, 17x16B quads)

// ---------------- device scratch (static: zero-initialized at load) ----------
__device__ float  g_bufA[(size_t)NMAX * CDIM];   // conv accumulators (fp32)
__device__ uint4  g_xh1[(size_t)NMAX * 8], g_xl1[(size_t)NMAX * 8]; // x split
__device__ uint4  g_xh2[(size_t)NMAX * 8], g_xl2[(size_t)NMAX * 8]; // act split
__device__ uint4  g_w1s[KSLOTS * 512], g_w2s[KSLOTS * 512]; // Wt fp16 hi only
__device__ int2   g_sij[EMAX];                   // sorted (target, source); pad=(-1,0)
__device__ int    g_hist[KSLOTS];                // invariant: 0 between calls
__device__ int    g_aoff[KSLOTS + 1];
__device__ int    g_cursor[KSLOTS];
__device__ int    g_segoff[MAXSEG + 1];
__device__ double g_s1[MAXSEG], g_s2[MAXSEG];
__device__ float  g_mean[MAXSEG], g_invs[MAXSEG];

// ---------------- helpers -----------------------------------------------------
__device__ __forceinline__ uint32_t smem_u32(const void* p) {
    uint32_t a;
    asm("{ .reg .u64 t; cvta.to.shared.u64 t, %1; cvt.u32.u64 %0, t; }"
        : "=r"(a) : "l"(p));
    return a;
}
__device__ __forceinline__ void cpa16(uint32_t d, const void* s) {
    asm volatile("cp.async.cg.shared.global [%0], [%1], 16;"
                 :: "r"(d), "l"(s) : "memory");
}
#define CPA_COMMIT() asm volatile("cp.async.commit_group;" ::: "memory")
#define CPA_WAIT0()  asm volatile("cp.async.wait_group 0;" ::: "memory")

#define LDMX4(r, addr) \
    asm volatile("ldmatrix.sync.aligned.m8n8.x4.shared.b16 {%0,%1,%2,%3}, [%4];" \
        : "=r"((r)[0]), "=r"((r)[1]), "=r"((r)[2]), "=r"((r)[3]) : "r"(addr))

#define MMA16816F(d, a, b0, b1) \
    asm volatile("mma.sync.aligned.m16n8k16.row.col.f32.f16.f16.f32 " \
        "{%0,%1,%2,%3}, {%4,%5,%6,%7}, {%8,%9}, {%0,%1,%2,%3};" \
        : "+f"((d)[0]), "+f"((d)[1]), "+f"((d)[2]), "+f"((d)[3]) \
        : "r"((a)[0]), "r"((a)[1]), "r"((a)[2]), "r"((a)[3]), "r"(b0), "r"(b1))

// fp16 hi/lo split of a float pair -> packed u32s
__device__ __forceinline__ void split2(float a, float b, unsigned& h, unsigned& l) {
    __half ha = __float2half_rn(a), hb = __float2half_rn(b);
    float ra = a - __half2float(ha);
    float rb = b - __half2float(hb);
    __half la = __float2half_rn(ra), lb = __float2half_rn(rb);
    h = (unsigned)__half_as_ushort(ha) | ((unsigned)__half_as_ushort(hb) << 16);
    l = (unsigned)__half_as_ushort(la) | ((unsigned)__half_as_ushort(lb) << 16);
}

// ---------------- prep: pad fill + hist + x split + W transpose (fp16 hi) ----
__global__ void k_prep(const int* __restrict__ ek, int E, int fillN,
                       const float* __restrict__ x, int N,
                       const float* __restrict__ W1, const float* __restrict__ W2) {
    __shared__ int h[KSLOTS];
    if (threadIdx.x < KSLOTS) h[threadIdx.x] = 0;
    __syncthreads();
    int stride = gridDim.x * blockDim.x;
    int idx0   = blockIdx.x * blockDim.x + threadIdx.x;

    for (int e = idx0; e < fillN; e += stride) g_sij[e] = make_int2(-1, 0);
    for (int e = idx0; e < E; e += stride) atomicAdd(&h[ek[e]], 1);

    // x rows -> fp16 hi/lo
    for (int p = idx0; p < N; p += stride) {
        const float4* xr = reinterpret_cast<const float4*>(x + (size_t)p * CDIM);
        #pragma unroll
        for (int g = 0; g < 8; g++) {
            float4 a = __ldg(xr + 2 * g), b = __ldg(xr + 2 * g + 1);
            uint4 oh, ol;
            split2(a.x, a.y, oh.x, ol.x);
            split2(a.z, a.w, oh.y, ol.y);
            split2(b.x, b.y, oh.z, ol.z);
            split2(b.z, b.w, oh.w, ol.w);
            g_xh1[(size_t)p * 8 + g] = oh;
            g_xl1[(size_t)p * 8 + g] = ol;
        }
    }

    // W -> transposed Wt[o][c], fp16 hi only: per k, 4096 ushort
    int wtot = 2 * KSLOTS * CDIM * CDIM;
    for (int q = idx0; q < wtot; q += stride) {
        int which = (q >= KSLOTS * CDIM * CDIM);
        int rem   = which ? q - KSLOTS * CDIM * CDIM : q;
        int kk = rem >> 12;
        int cc = (rem & 4095) >> 6;
        int oo = rem & 63;
        const float* W = which ? W2 : W1;
        float v = __ldg(W + (size_t)kk * 4096 + cc * 64 + oo);
        unsigned short* dst = reinterpret_cast<unsigned short*>(which ? g_w2s : g_w1s);
        dst[(size_t)kk * 4096 + oo * 64 + cc] = __half_as_ushort(__float2half_rn(v));
    }

    __syncthreads();
    if (threadIdx.x < KSLOTS) atomicAdd(&g_hist[threadIdx.x], h[threadIdx.x]);
}

__global__ void k_scan(const int* __restrict__ ss, int B, int N) {
    if (threadIdx.x == 0 && blockIdx.x == 0) {
        int off = 0;
        for (int q = 0; q < KSLOTS; q++) {
            g_aoff[q]   = off;
            g_cursor[q] = off;
            off += ((g_hist[q] + TILE - 1) / TILE) * TILE;
        }
        g_aoff[KSLOTS] = off;
        int p = 0;
        for (int b = 0; b < B; b++) { g_segoff[b] = p; p += ss[b]; }
        g_segoff[B] = N;
        for (int b = 0; b < B; b++) { g_s1[b] = 0.0; g_s2[b] = 0.0; }
    }
}

// block-aggregated counting-sort scatter: 1 global atomic per (block, slot)
__global__ void k_scatter(const int* __restrict__ i, const int* __restrict__ j,
                          const int* __restrict__ k, int E) {
    __shared__ int sh[KSLOTS], sbase[KSLOTS];
    int tid = threadIdx.x;
    if (tid < KSLOTS) sh[tid] = 0;
    __syncthreads();
    int e = blockIdx.x * blockDim.x + tid;
    int kk = 0, rank = 0;
    bool valid = (e < E);
    if (valid) {
        kk   = k[e];
        rank = atomicAdd(&sh[kk], 1);
    }
    __syncthreads();
    if (tid < KSLOTS && sh[tid] > 0)
        sbase[tid] = atomicAdd(&g_cursor[tid], sh[tid]);
    __syncthreads();
    if (valid) {
        int pos = sbase[kk] + rank;
        g_sij[pos] = make_int2(i[e], j[e]);
    }
    if (blockIdx.x == 0 && tid < KSLOTS) g_hist[tid] = 0;   // reset for replay
}

// ---------------- tensor-core conv (mma.sync fp16 split, 2-term) -------------
// Tile = 128 edges x 64 outputs. Warp w: edges [32w,32w+32) x all 64 outputs.
// D = Xh*Wh + Xl*Wh (fp16 hi/lo of X, fp16 W; fp32 accumulate).
// Coalesced cp.async gather; epilogue routes D through smem (reusing the X
// buffer) so REDs are 16-lanes-per-row coalesced.
__global__ void __launch_bounds__(128)
k_conv(const uint4* __restrict__ gXh, const uint4* __restrict__ gXl,
       const uint4* __restrict__ gW, float* __restrict__ out) {
    extern __shared__ char smem[];
    int tb = blockIdx.x * TILE;
    if (tb >= g_aoff[KSLOTS]) return;
    int kk = 0;
    while (g_aoff[kk + 1] <= tb) kk++;

    int tid = threadIdx.x, w = tid >> 5, lane = tid & 31;
    uint32_t sb = smem_u32(smem);

    // stage Wt[k] hi (rows o, stride 144B) via cp.async (coalesced)
    const uint4* ws = gW + (size_t)kk * 512;
    #pragma unroll
    for (int q = 0; q < 4; q++) {
        int idx = tid + 128 * q;
        int o = idx >> 3, c8 = idx & 7;
        cpa16(sb + SM_WH + o * 144 + c8 * 16, ws + idx);
    }
    // coalesced gather: row = idx>>3, chunk = idx&7; 8 lanes cover one row
    #pragma unroll
    for (int q = 0; q < 8; q++) {
        int idx = tid + 128 * q;
        int row = idx >> 3, ch = idx & 7;
        int jj  = g_sij[tb + row].y;          // 8-lane broadcast load
        cpa16(sb + SM_XH + row * 144 + ch * 16, gXh + (size_t)jj * 8 + ch);
        cpa16(sb + SM_XL + row * 144 + ch * 16, gXl + (size_t)jj * 8 + ch);
    }
    CPA_COMMIT();
    CPA_WAIT0();
    __syncthreads();

    float acc[2][8][4];
    #pragma unroll
    for (int a = 0; a < 2; a++)
        #pragma unroll
        for (int b = 0; b < 8; b++)
            #pragma unroll
            for (int c = 0; c < 4; c++) acc[a][b][c] = 0.f;

    // per-lane ldmatrix base addresses
    uint32_t aH[2], aL[2], bH[4];
    {
        int arow  = lane & 15;
        int abyte = (lane >> 4) * 16;          // k-half select
        #pragma unroll
        for (int mt = 0; mt < 2; mt++) {
            int row = w * 32 + mt * 16 + arow;
            aH[mt] = sb + SM_XH + row * 144 + abyte;
            aL[mt] = sb + SM_XL + row * 144 + abyte;
        }
        int nsub  = (lane & 7) + 8 * (lane >> 4);   // n within 16-octet pair
        int kbyte = ((lane >> 3) & 1) * 16;         // k-half select
        #pragma unroll
        for (int np = 0; np < 4; np++) {
            int nn = np * 16 + nsub;
            bH[np] = sb + SM_WH + nn * 144 + kbyte;
        }
    }

    #pragma unroll
    for (int ks = 0; ks < 4; ks++) {
        uint32_t ah[2][4], al[2][4];
        #pragma unroll
        for (int mt = 0; mt < 2; mt++) {
            LDMX4(ah[mt], aH[mt] + ks * 32);
            LDMX4(al[mt], aL[mt] + ks * 32);
        }
        #pragma unroll
        for (int np = 0; np < 4; np++) {
            uint32_t bh[4];
            LDMX4(bh, bH[np] + ks * 32);
            #pragma unroll
            for (int mt = 0; mt < 2; mt++) {
                float* d0 = acc[mt][2 * np];
                float* d1 = acc[mt][2 * np + 1];
                MMA16816F(d0, ah[mt], bh[0], bh[1]);
                MMA16816F(d0, al[mt], bh[0], bh[1]);
                MMA16816F(d1, ah[mt], bh[2], bh[3]);
                MMA16816F(d1, al[mt], bh[2], bh[3]);
            }
        }
    }

    // ---- epilogue: transpose D through smem (reuse X region), coalesced RED
    __syncthreads();   // all warps done reading X smem
    float* Dst = reinterpret_cast<float*>(smem);   // [128][68] floats
    {
        int r0 = w * 32 + (lane >> 2);
        int cb = (lane & 3) * 2;
        #pragma unroll
        for (int mt = 0; mt < 2; mt++) {
            int r = r0 + mt * 16;
            #pragma unroll
            for (int nt = 0; nt < 8; nt++) {
                int c = nt * 8 + cb;
                *reinterpret_cast<float2*>(Dst + r * DSTRIDE + c) =
                    make_float2(acc[mt][nt][0], acc[mt][nt][1]);
                *reinterpret_cast<float2*>(Dst + (r + 8) * DSTRIDE + c) =
                    make_float2(acc[mt][nt][2], acc[mt][nt][3]);
            }
        }
    }
    __syncthreads();

    // 16 lanes cover one 256B output row -> 2 rows per warp inst (coalesced)
    {
        int rbase = tid >> 4;        // 0..7
        int ch    = tid & 15;        // 16B chunk within row
        #pragma unroll
        for (int s = 0; s < 16; s++) {
            int row = rbase + 8 * s;
            int ii  = g_sij[tb + row].x;
            if (ii >= 0) {
                float4 v = *reinterpret_cast<float4*>(Dst + row * DSTRIDE + ch * 4);
                atomicAdd(reinterpret_cast<float4*>(out + (size_t)ii * CDIM) + ch, v);
            }
        }
    }
}

// ---------------- ragged LayerNorm ------------------------------------------
__global__ void k_stats(const float* __restrict__ v) {
    int seg = blockIdx.x;
    long long e0 = (long long)g_segoff[seg] * CDIM;
    long long e1 = (long long)g_segoff[seg + 1] * CDIM;
    double s1 = 0.0, s2 = 0.0;
    long long stride = (long long)gridDim.y * blockDim.x;
    for (long long idx = e0 + (long long)blockIdx.y * blockDim.x + threadIdx.x;
         idx < e1; idx += stride) {
        double d = (double)v[idx];
        s1 += d;
        s2 += d * d;
    }
    #pragma unroll
    for (int o = 16; o; o >>= 1) {
        s1 += __shfl_down_sync(0xffffffffu, s1, o);
        s2 += __shfl_down_sync(0xffffffffu, s2, o);
    }
    __shared__ double w1[8], w2[8];
    int wid = threadIdx.x >> 5, lid = threadIdx.x & 31;
    if (lid == 0) { w1[wid] = s1; w2[wid] = s2; }
    __syncthreads();
    if (threadIdx.x == 0) {
        double a = 0.0, b = 0.0;
        int nw = blockDim.x >> 5;
        for (int q = 0; q < nw; q++) { a += w1[q]; b += w2[q]; }
        atomicAdd(&g_s1[seg], a);
        atomicAdd(&g_s2[seg], b);
    }
}

__global__ void k_finalize(int B) {
    int s = blockIdx.x * blockDim.x + threadIdx.x;
    if (s < B) {
        double cnt  = (double)(g_segoff[s + 1] - g_segoff[s]) * (double)CDIM;
        double mean = g_s1[s] / cnt;
        double var  = g_s2[s] / cnt - mean * mean;
        g_mean[s] = (float)mean;
        g_invs[s] = rsqrtf((float)var + 1e-5f);
    }
}

__device__ __forceinline__ int find_seg(int p, int B) {
    int s = 0;
    #pragma unroll 1
    while (s + 1 < B && __ldg(&g_segoff[s + 1]) <= p) s++;
    return s;
}

// LN1 + relu -> fp16 hi/lo split; re-zeroes accumulator + layer-2 stats
__global__ void k_norm_relu(float* __restrict__ v,
                            const float* __restrict__ gamma,
                            const float* __restrict__ beta,
                            uint4* __restrict__ oh, uint4* __restrict__ ol,
                            int N, int B) {
    if (blockIdx.x == 0 && threadIdx.x < B) {
        g_s1[threadIdx.x] = 0.0;
        g_s2[threadIdx.x] = 0.0;
    }
    int total = N * (CDIM / 4);
    float4 z = make_float4(0.f, 0.f, 0.f, 0.f);
    for (int q = blockIdx.x * blockDim.x + threadIdx.x; q < total;
         q += gridDim.x * blockDim.x) {
        int p  = q >> 4;
        int c4 = (q & 15) << 2;
        int s  = find_seg(p, B);
        float mu = g_mean[s], inv = g_invs[s];
        float4 x4 = reinterpret_cast<float4*>(v)[q];
        reinterpret_cast<float4*>(v)[q] = z;   // re-zero for conv2
        float4 gg = __ldg(reinterpret_cast<const float4*>(gamma + c4));
        float4 bb = __ldg(reinterpret_cast<const float4*>(beta + c4));
        float r0 = fmaxf(fmaf((x4.x - mu) * inv, gg.x, bb.x), 0.f);
        float r1 = fmaxf(fmaf((x4.y - mu) * inv, gg.y, bb.y), 0.f);
        float r2 = fmaxf(fmaf((x4.z - mu) * inv, gg.z, bb.z), 0.f);
        float r3 = fmaxf(fmaf((x4.w - mu) * inv, gg.w, bb.w), 0.f);
        uint2 hh, ll;
        split2(r0, r1, hh.x, ll.x);
        split2(r2, r3, hh.y, ll.y);
        reinterpret_cast<uint2*>(oh)[(size_t)p * 16 + (q & 15)] = hh;
        reinterpret_cast<uint2*>(ol)[(size_t)p * 16 + (q & 15)] = ll;
    }
}

// LN2 + residual + relu; re-zeroes accumulator for the next replay
__global__ void k_norm_res_relu(float* __restrict__ v,
                                const float* __restrict__ gamma,
                                const float* __restrict__ beta,
                                const float* __restrict__ xin,
                                float* __restrict__ o, int N, int B) {
    int total = N * (CDIM / 4);
    float4 z = make_float4(0.f, 0.f, 0.f, 0.f);
    for (int q = blockIdx.x * blockDim.x + threadIdx.x; q < total;
         q += gridDim.x * blockDim.x) {
        int p  = q >> 4;
        int c4 = (q & 15) << 2;
        int s  = find_seg(p, B);
        float mu = g_mean[s], inv = g_invs[s];
        float4 x4 = reinterpret_cast<float4*>(v)[q];
        reinterpret_cast<float4*>(v)[q] = z;   // re-zero for next call
        float4 rx = __ldg(reinterpret_cast<const float4*>(xin) + q);
        float4 gg = __ldg(reinterpret_cast<const float4*>(gamma + c4));
        float4 bb = __ldg(reinterpret_cast<const float4*>(beta + c4));
        float4 r;
        r.x = fmaxf(fmaf((x4.x - mu) * inv, gg.x, bb.x) + rx.x, 0.f);
        r.y = fmaxf(fmaf((x4.y - mu) * inv, gg.y, bb.y) + rx.y, 0.f);
        r.z = fmaxf(fmaf((x4.z - mu) * inv, gg.z, bb.z) + rx.z, 0.f);
        r.w = fmaxf(fmaf((x4.w - mu) * inv, gg.w, bb.w) + rx.w, 0.f);
        reinterpret_cast<float4*>(o)[q] = r;
    }
}

// ---------------- host-side launch sequence ---------------------------------
extern "C" void kernel_launch(void* const* d_in, const int* in_sizes, int n_in,
                              void* d_out, int out_size) {
    (void)n_in; (void)out_size;
    const float* x  = (const float*)d_in[0];
    const float* W1 = (const float*)d_in[1];
    const float* g1 = (const float*)d_in[2];
    const float* b1 = (const float*)d_in[3];
    const float* W2 = (const float*)d_in[4];
    const float* g2 = (const float*)d_in[5];
    const float* b2 = (const float*)d_in[6];
    const int*   ei = (const int*)d_in[7];
    const int*   ej = (const int*)d_in[8];
    const int*   ek = (const int*)d_in[9];
    const int*   ss = (const int*)d_in[10];

    int N = in_sizes[0] / CDIM;
    int E = in_sizes[7];
    int B = in_sizes[10];
    float* out = (float*)d_out;

    float* pA; cudaGetSymbolAddress((void**)&pA, g_bufA);
    uint4 *xh1, *xl1, *xh2, *xl2, *w1s, *w2s;
    cudaGetSymbolAddress((void**)&xh1, g_xh1);
    cudaGetSymbolAddress((void**)&xl1, g_xl1);
    cudaGetSymbolAddress((void**)&xh2, g_xh2);
    cudaGetSymbolAddress((void**)&xl2, g_xl2);
    cudaGetSymbolAddress((void**)&w1s, g_w1s);
    cudaGetSymbolAddress((void**)&w2s, g_w2s);

    cudaFuncSetAttribute(k_conv, cudaFuncAttributeMaxDynamicSharedMemorySize, SMEM_TOT);

    int fillN = E + EPAD; if (fillN > EMAX) fillN = EMAX;
    int statB = (B + 31) / 32;
    int sgrid = (E + 255) / 256;
    int nb    = (E + KSLOTS * (TILE - 1) + TILE - 1) / TILE;

    // replay-state invariants: g_hist=0 (end of k_scatter), g_bufA=0 (LN epilogues)
    k_prep<<<1024, 256>>>(ek, E, fillN, x, N, W1, W2);            // L1
    k_scan<<<1, 1>>>(ss, B, N);                                    // L2
    k_scatter<<<sgrid, 256>>>(ei, ej, ek, E);                      // L3

    k_conv<<<nb, 128, SMEM_TOT>>>(xh1, xl1, w1s, pA);              // L4 (profiled)
    k_stats<<<dim3(B, 128), 256>>>(pA);                            // L5
    k_finalize<<<statB, 32>>>(B);                                  // L6
    k_norm_relu<<<512, 256>>>(pA, g1, b1, xh2, xl2, N, B);         // L7

    k_conv<<<nb, 128, SMEM_TOT>>>(xh2, xl2, w2s, pA);              // L8
    k_stats<<<dim3(B, 128), 256>>>(pA);                            // L9
    k_finalize<<<statB, 32>>>(B);                                  // L10
    k_norm_res_relu<<<512, 256>>>(pA, g2, b2, x, out, N, B);       // L11
}

// round 13
// speedup vs baseline: 2.2940x; 1.2181x over previous
#include <cuda_runtime.h>
#include <cuda_fp16.h>
#include <cstdint>

#define CDIM     64
#define KSLOTS   27
#define TILE     128
#define NMAX     65536
#define EPAD     (KSLOTS * TILE)
#define EMAX     (1572864 + EPAD)
#define MAXSEG   1024

// smem: XOR-swizzled X (16KB) + W (8KB); D epilogue buffer (34816B) overlays.
#define SM_X     0
#define SM_W     16384
#define SMEM_TOT 34816
#define DSTRIDE  68            // D row stride in floats (272B)

// ---------------- device scratch (static: zero-initialized at load) ----------
__device__ float  g_bufA[(size_t)NMAX * CDIM];   // conv accumulators (fp32)
__device__ uint4  g_xh1[(size_t)NMAX * 8];       // x fp16 rows (128B each)
__device__ uint4  g_xh2[(size_t)NMAX * 8];       // act fp16 rows
__device__ uint4  g_w1s[KSLOTS * 512], g_w2s[KSLOTS * 512]; // Wt fp16
__device__ int2   g_sij[EMAX];                   // sorted (target, source); pad=(-1,0)
__device__ int    g_hist[KSLOTS];                // invariant: 0 between calls
__device__ int    g_aoff[KSLOTS + 1];
__device__ int    g_cursor[KSLOTS];
__device__ int    g_segoff[MAXSEG + 1];
__device__ double g_s1[MAXSEG], g_s2[MAXSEG];
__device__ float  g_mean[MAXSEG], g_invs[MAXSEG];

// ---------------- helpers -----------------------------------------------------
__device__ __forceinline__ uint32_t smem_u32(const void* p) {
    uint32_t a;
    asm("{ .reg .u64 t; cvta.to.shared.u64 t, %1; cvt.u32.u64 %0, t; }"
        : "=r"(a) : "l"(p));
    return a;
}
__device__ __forceinline__ void cpa16(uint32_t d, const void* s) {
    asm volatile("cp.async.cg.shared.global [%0], [%1], 16;"
                 :: "r"(d), "l"(s) : "memory");
}
#define CPA_COMMIT() asm volatile("cp.async.commit_group;" ::: "memory")
#define CPA_WAIT0()  asm volatile("cp.async.wait_group 0;" ::: "memory")

#define LDMX4(r, addr) \
    asm volatile("ldmatrix.sync.aligned.m8n8.x4.shared.b16 {%0,%1,%2,%3}, [%4];" \
        : "=r"((r)[0]), "=r"((r)[1]), "=r"((r)[2]), "=r"((r)[3]) : "r"(addr))

#define MMA16816F(d, a, b0, b1) \
    asm volatile("mma.sync.aligned.m16n8k16.row.col.f32.f16.f16.f32 " \
        "{%0,%1,%2,%3}, {%4,%5,%6,%7}, {%8,%9}, {%0,%1,%2,%3};" \
        : "+f"((d)[0]), "+f"((d)[1]), "+f"((d)[2]), "+f"((d)[3]) \
        : "r"((a)[0]), "r"((a)[1]), "r"((a)[2]), "r"((a)[3]), "r"(b0), "r"(b1))

// fp16 convert of a float pair -> packed u32
__device__ __forceinline__ unsigned cvt2(float a, float b) {
    __half ha = __float2half_rn(a), hb = __float2half_rn(b);
    return (unsigned)__half_as_ushort(ha) | ((unsigned)__half_as_ushort(hb) << 16);
}

// ---------------- prep: pad fill + hist + x fp16 + W transpose (fp16) --------
__global__ void k_prep(const int* __restrict__ ek, int E, int fillN,
                       const float* __restrict__ x, int N,
                       const float* __restrict__ W1, const float* __restrict__ W2) {
    __shared__ int h[KSLOTS];
    if (threadIdx.x < KSLOTS) h[threadIdx.x] = 0;
    __syncthreads();
    int stride = gridDim.x * blockDim.x;
    int idx0   = blockIdx.x * blockDim.x + threadIdx.x;

    for (int e = idx0; e < fillN; e += stride) g_sij[e] = make_int2(-1, 0);
    for (int e = idx0; e < E; e += stride) atomicAdd(&h[ek[e]], 1);

    // x rows -> fp16
    for (int p = idx0; p < N; p += stride) {
        const float4* xr = reinterpret_cast<const float4*>(x + (size_t)p * CDIM);
        #pragma unroll
        for (int g = 0; g < 8; g++) {
            float4 a = __ldg(xr + 2 * g), b = __ldg(xr + 2 * g + 1);
            uint4 oh;
            oh.x = cvt2(a.x, a.y);
            oh.y = cvt2(a.z, a.w);
            oh.z = cvt2(b.x, b.y);
            oh.w = cvt2(b.z, b.w);
            g_xh1[(size_t)p * 8 + g] = oh;
        }
    }

    // W -> transposed Wt[o][c], fp16: per k, 4096 ushort
    int wtot = 2 * KSLOTS * CDIM * CDIM;
    for (int q = idx0; q < wtot; q += stride) {
        int which = (q >= KSLOTS * CDIM * CDIM);
        int rem   = which ? q - KSLOTS * CDIM * CDIM : q;
        int kk = rem >> 12;
        int cc = (rem & 4095) >> 6;
        int oo = rem & 63;
        const float* W = which ? W2 : W1;
        float v = __ldg(W + (size_t)kk * 4096 + cc * 64 + oo);
        unsigned short* dst = reinterpret_cast<unsigned short*>(which ? g_w2s : g_w1s);
        dst[(size_t)kk * 4096 + oo * 64 + cc] = __half_as_ushort(__float2half_rn(v));
    }

    __syncthreads();
    if (threadIdx.x < KSLOTS) atomicAdd(&g_hist[threadIdx.x], h[threadIdx.x]);
}

__global__ void k_scan(const int* __restrict__ ss, int B, int N) {
    if (threadIdx.x == 0 && blockIdx.x == 0) {
        int off = 0;
        for (int q = 0; q < KSLOTS; q++) {
            g_aoff[q]   = off;
            g_cursor[q] = off;
            off += ((g_hist[q] + TILE - 1) / TILE) * TILE;
        }
        g_aoff[KSLOTS] = off;
        int p = 0;
        for (int b = 0; b < B; b++) { g_segoff[b] = p; p += ss[b]; }
        g_segoff[B] = N;
        for (int b = 0; b < B; b++) { g_s1[b] = 0.0; g_s2[b] = 0.0; }
    }
}

// block-aggregated counting-sort scatter: 1 global atomic per (block, slot)
__global__ void k_scatter(const int* __restrict__ i, const int* __restrict__ j,
                          const int* __restrict__ k, int E) {
    __shared__ int sh[KSLOTS], sbase[KSLOTS];
    int tid = threadIdx.x;
    if (tid < KSLOTS) sh[tid] = 0;
    __syncthreads();
    int e = blockIdx.x * blockDim.x + tid;
    int kk = 0, rank = 0;
    bool valid = (e < E);
    if (valid) {
        kk   = k[e];
        rank = atomicAdd(&sh[kk], 1);
    }
    __syncthreads();
    if (tid < KSLOTS && sh[tid] > 0)
        sbase[tid] = atomicAdd(&g_cursor[tid], sh[tid]);
    __syncthreads();
    if (valid) {
        int pos = sbase[kk] + rank;
        g_sij[pos] = make_int2(i[e], j[e]);
    }
    if (blockIdx.x == 0 && tid < KSLOTS) g_hist[tid] = 0;   // reset for replay
}

// ---------------- tensor-core conv (mma.sync fp16 single-term) ---------------
// Tile = 128 edges x 64 outputs. Warp w: edges [32w,32w+32) x all 64 outputs.
// XOR-swizzled smem (chunk ^= row&7): no padding, conflict-free STS/ldmatrix.
// Epilogue routes D through smem (overlaying X+W) for coalesced float4 REDs.
__global__ void __launch_bounds__(128, 5)
k_conv(const uint4* __restrict__ gX, const uint4* __restrict__ gW,
       float* __restrict__ out) {
    extern __shared__ char smem[];
    int tb = blockIdx.x * TILE;
    if (tb >= g_aoff[KSLOTS]) return;
    int kk = 0;
    while (g_aoff[kk + 1] <= tb) kk++;

    int tid = threadIdx.x, w = tid >> 5, lane = tid & 31;
    uint32_t sb = smem_u32(smem);

    // stage Wt[k] (64 rows x 128B, swizzled) via cp.async
    const uint4* ws = gW + (size_t)kk * 512;
    #pragma unroll
    for (int q = 0; q < 4; q++) {
        int idx = tid + 128 * q;
        int o = idx >> 3, c8 = idx & 7;
        cpa16(sb + SM_W + o * 128 + ((c8 ^ (o & 7)) << 4), ws + idx);
    }
    // coalesced gather: 8 lanes cover one row's 128B (swizzled dst)
    #pragma unroll
    for (int q = 0; q < 8; q++) {
        int idx = tid + 128 * q;
        int row = idx >> 3, ch = idx & 7;
        int jj  = g_sij[tb + row].y;          // 8-lane broadcast load
        cpa16(sb + SM_X + row * 128 + ((ch ^ (row & 7)) << 4),
              gX + (size_t)jj * 8 + ch);
    }
    CPA_COMMIT();
    CPA_WAIT0();
    __syncthreads();

    float acc[2][8][4];
    #pragma unroll
    for (int a = 0; a < 2; a++)
        #pragma unroll
        for (int b = 0; b < 8; b++)
            #pragma unroll
            for (int c = 0; c < 4; c++) acc[a][b][c] = 0.f;

    int arow  = lane & 15;
    int achk0 = lane >> 4;                       // A chunk base (k-half)
    int nsub  = (lane & 7) + 8 * (lane >> 4);    // B n within 16-octet pair
    int bchk0 = (lane >> 3) & 1;                 // B chunk base (k-half)

    #pragma unroll
    for (int ks = 0; ks < 4; ks++) {
        uint32_t ah[2][4];
        #pragma unroll
        for (int mt = 0; mt < 2; mt++) {
            int row = w * 32 + mt * 16 + arow;
            int chk = (achk0 + 2 * ks) ^ (row & 7);
            LDMX4(ah[mt], sb + SM_X + row * 128 + (chk << 4));
        }
        #pragma unroll
        for (int np = 0; np < 4; np++) {
            int nn  = np * 16 + nsub;
            int chk = (bchk0 + 2 * ks) ^ (nn & 7);
            uint32_t bh[4];
            LDMX4(bh, sb + SM_W + nn * 128 + (chk << 4));
            #pragma unroll
            for (int mt = 0; mt < 2; mt++) {
                MMA16816F(acc[mt][2 * np],     ah[mt], bh[0], bh[1]);
                MMA16816F(acc[mt][2 * np + 1], ah[mt], bh[2], bh[3]);
            }
        }
    }

    // ---- epilogue: transpose D through smem (overlay X+W), coalesced RED
    __syncthreads();   // all warps done reading X/W smem
    float* Dst = reinterpret_cast<float*>(smem);   // [128][68] floats
    {
        int r0 = w * 32 + (lane >> 2);
        int cb = (lane & 3) * 2;
        #pragma unroll
        for (int mt = 0; mt < 2; mt++) {
            int r = r0 + mt * 16;
            #pragma unroll
            for (int nt = 0; nt < 8; nt++) {
                int c = nt * 8 + cb;
                *reinterpret_cast<float2*>(Dst + r * DSTRIDE + c) =
                    make_float2(acc[mt][nt][0], acc[mt][nt][1]);
                *reinterpret_cast<float2*>(Dst + (r + 8) * DSTRIDE + c) =
                    make_float2(acc[mt][nt][2], acc[mt][nt][3]);
            }
        }
    }
    __syncthreads();

    // 16 lanes cover one 256B output row -> coalesced float4 REDs
    {
        int rbase = tid >> 4;        // 0..7
        int ch    = tid & 15;        // 16B chunk within row
        #pragma unroll
        for (int s = 0; s < 16; s++) {
            int row = rbase + 8 * s;
            int ii  = g_sij[tb + row].x;
            if (ii >= 0) {
                float4 v = *reinterpret_cast<float4*>(Dst + row * DSTRIDE + ch * 4);
                atomicAdd(reinterpret_cast<float4*>(out + (size_t)ii * CDIM) + ch, v);
            }
        }
    }
}

// ---------------- ragged LayerNorm ------------------------------------------
__global__ void k_stats(const float* __restrict__ v) {
    int seg = blockIdx.x;
    long long e0 = (long long)g_segoff[seg] * CDIM;
    long long e1 = (long long)g_segoff[seg + 1] * CDIM;
    double s1 = 0.0, s2 = 0.0;
    long long stride = (long long)gridDim.y * blockDim.x;
    for (long long idx = e0 + (long long)blockIdx.y * blockDim.x + threadIdx.x;
         idx < e1; idx += stride) {
        double d = (double)v[idx];
        s1 += d;
        s2 += d * d;
    }
    #pragma unroll
    for (int o = 16; o; o >>= 1) {
        s1 += __shfl_down_sync(0xffffffffu, s1, o);
        s2 += __shfl_down_sync(0xffffffffu, s2, o);
    }
    __shared__ double w1[8], w2[8];
    int wid = threadIdx.x >> 5, lid = threadIdx.x & 31;
    if (lid == 0) { w1[wid] = s1; w2[wid] = s2; }
    __syncthreads();
    if (threadIdx.x == 0) {
        double a = 0.0, b = 0.0;
        int nw = blockDim.x >> 5;
        for (int q = 0; q < nw; q++) { a += w1[q]; b += w2[q]; }
        atomicAdd(&g_s1[seg], a);
        atomicAdd(&g_s2[seg], b);
    }
}

__global__ void k_finalize(int B) {
    int s = blockIdx.x * blockDim.x + threadIdx.x;
    if (s < B) {
        double cnt  = (double)(g_segoff[s + 1] - g_segoff[s]) * (double)CDIM;
        double mean = g_s1[s] / cnt;
        double var  = g_s2[s] / cnt - mean * mean;
        g_mean[s] = (float)mean;
        g_invs[s] = rsqrtf((float)var + 1e-5f);
    }
}

__device__ __forceinline__ int find_seg(int p, int B) {
    int s = 0;
    #pragma unroll 1
    while (s + 1 < B && __ldg(&g_segoff[s + 1]) <= p) s++;
    return s;
}

// LN1 + relu -> fp16; re-zeroes accumulator + layer-2 stats
__global__ void k_norm_relu(float* __restrict__ v,
                            const float* __restrict__ gamma,
                            const float* __restrict__ beta,
                            uint4* __restrict__ oh, int N, int B) {
    if (blockIdx.x == 0 && threadIdx.x < B) {
        g_s1[threadIdx.x] = 0.0;
        g_s2[threadIdx.x] = 0.0;
    }
    int total = N * (CDIM / 4);
    float4 z = make_float4(0.f, 0.f, 0.f, 0.f);
    for (int q = blockIdx.x * blockDim.x + threadIdx.x; q < total;
         q += gridDim.x * blockDim.x) {
        int p  = q >> 4;
        int c4 = (q & 15) << 2;
        int s  = find_seg(p, B);
        float mu = g_mean[s], inv = g_invs[s];
        float4 x4 = reinterpret_cast<float4*>(v)[q];
        reinterpret_cast<float4*>(v)[q] = z;   // re-zero for conv2
        float4 gg = __ldg(reinterpret_cast<const float4*>(gamma + c4));
        float4 bb = __ldg(reinterpret_cast<const float4*>(beta + c4));
        float r0 = fmaxf(fmaf((x4.x - mu) * inv, gg.x, bb.x), 0.f);
        float r1 = fmaxf(fmaf((x4.y - mu) * inv, gg.y, bb.y), 0.f);
        float r2 = fmaxf(fmaf((x4.z - mu) * inv, gg.z, bb.z), 0.f);
        float r3 = fmaxf(fmaf((x4.w - mu) * inv, gg.w, bb.w), 0.f);
        uint2 hh;
        hh.x = cvt2(r0, r1);
        hh.y = cvt2(r2, r3);
        reinterpret_cast<uint2*>(oh)[(size_t)p * 16 + (q & 15)] = hh;
    }
}

// LN2 + residual + relu; re-zeroes accumulator for the next replay
__global__ void k_norm_res_relu(float* __restrict__ v,
                                const float* __restrict__ gamma,
                                const float* __restrict__ beta,
                                const float* __restrict__ xin,
                                float* __restrict__ o, int N, int B) {
    int total = N * (CDIM / 4);
    float4 z = make_float4(0.f, 0.f, 0.f, 0.f);
    for (int q = blockIdx.x * blockDim.x + threadIdx.x; q < total;
         q += gridDim.x * blockDim.x) {
        int p  = q >> 4;
        int c4 = (q & 15) << 2;
        int s  = find_seg(p, B);
        float mu = g_mean[s], inv = g_invs[s];
        float4 x4 = reinterpret_cast<float4*>(v)[q];
        reinterpret_cast<float4*>(v)[q] = z;   // re-zero for next call
        float4 rx = __ldg(reinterpret_cast<const float4*>(xin) + q);
        float4 gg = __ldg(reinterpret_cast<const float4*>(gamma + c4));
        float4 bb = __ldg(reinterpret_cast<const float4*>(beta + c4));
        float4 r;
        r.x = fmaxf(fmaf((x4.x - mu) * inv, gg.x, bb.x) + rx.x, 0.f);
        r.y = fmaxf(fmaf((x4.y - mu) * inv, gg.y, bb.y) + rx.y, 0.f);
        r.z = fmaxf(fmaf((x4.z - mu) * inv, gg.z, bb.z) + rx.z, 0.f);
        r.w = fmaxf(fmaf((x4.w - mu) * inv, gg.w, bb.w) + rx.w, 0.f);
        reinterpret_cast<float4*>(o)[q] = r;
    }
}

// ---------------- host-side launch sequence ---------------------------------
extern "C" void kernel_launch(void* const* d_in, const int* in_sizes, int n_in,
                              void* d_out, int out_size) {
    (void)n_in; (void)out_size;
    const float* x  = (const float*)d_in[0];
    const float* W1 = (const float*)d_in[1];
    const float* g1 = (const float*)d_in[2];
    const float* b1 = (const float*)d_in[3];
    const float* W2 = (const float*)d_in[4];
    const float* g2 = (const float*)d_in[5];
    const float* b2 = (const float*)d_in[6];
    const int*   ei = (const int*)d_in[7];
    const int*   ej = (const int*)d_in[8];
    const int*   ek = (const int*)d_in[9];
    const int*   ss = (const int*)d_in[10];

    int N = in_sizes[0] / CDIM;
    int E = in_sizes[7];
    int B = in_sizes[10];
    float* out = (float*)d_out;

    float* pA; cudaGetSymbolAddress((void**)&pA, g_bufA);
    uint4 *xh1, *xh2, *w1s, *w2s;
    cudaGetSymbolAddress((void**)&xh1, g_xh1);
    cudaGetSymbolAddress((void**)&xh2, g_xh2);
    cudaGetSymbolAddress((void**)&w1s, g_w1s);
    cudaGetSymbolAddress((void**)&w2s, g_w2s);

    cudaFuncSetAttribute(k_conv, cudaFuncAttributeMaxDynamicSharedMemorySize, SMEM_TOT);

    int fillN = E + EPAD; if (fillN > EMAX) fillN = EMAX;
    int statB = (B + 31) / 32;
    int sgrid = (E + 255) / 256;
    int nb    = (E + KSLOTS * (TILE - 1) + TILE - 1) / TILE;

    // replay-state invariants: g_hist=0 (end of k_scatter), g_bufA=0 (LN epilogues)
    k_prep<<<1024, 256>>>(ek, E, fillN, x, N, W1, W2);            // L1
    k_scan<<<1, 1>>>(ss, B, N);                                    // L2
    k_scatter<<<sgrid, 256>>>(ei, ej, ek, E);                      // L3

    k_conv<<<nb, 128, SMEM_TOT>>>(xh1, w1s, pA);                   // L4 (profiled)
    k_stats<<<dim3(B, 128), 256>>>(pA);                            // L5
    k_finalize<<<statB, 32>>>(B);                                  // L6
    k_norm_relu<<<512, 256>>>(pA, g1, b1, xh2, N, B);              // L7

    k_conv<<<nb, 128, SMEM_TOT>>>(xh2, w2s, pA);                   // L8
    k_stats<<<dim3(B, 128), 256>>>(pA);                            // L9
    k_finalize<<<statB, 32>>>(B);                                  // L10
    k_norm_res_relu<<<512, 256>>>(pA, g2, b2, x, out, N, B);       // L11
}